// round 1
// baseline (speedup 1.0000x reference)
#include <cuda_runtime.h>
#include <math.h>

// Problem constants
#define BB 4
#define TT 2048
#define CC 1024
#define HH 16
#define DD 64
// M = BB*TT = 8192

// Scratch (allocation-free rule: __device__ globals)
__device__ float g_qkv[(size_t)BB * TT * 3 * CC];  // [B,T,3C] = 8192 x 3072
__device__ float g_ctx[(size_t)BB * TT * CC];      // [B,T,C]  = 8192 x 1024

// ----------------------------------------------------------------------------
// SGEMM: C[M,N] = A[M,K] @ W[K,N] (+ bias). BM=BN=128, BK=16, 256 thr, 8x8 micro
// M,N,K all multiples of tile dims for this problem (8192 x {3072,1024} x 1024).
// ----------------------------------------------------------------------------
template <bool BIAS>
__global__ __launch_bounds__(256, 2)
void sgemm128(const float* __restrict__ A, const float* __restrict__ W,
              const float* __restrict__ bias, float* __restrict__ Cout,
              int M, int N, int K)
{
    __shared__ float As[16][128];  // transposed: As[k][m]
    __shared__ float Bs[16][128];  // Bs[k][n]

    const int tid = threadIdx.x;
    const int tx = tid & 15;   // n direction (16)
    const int ty = tid >> 4;   // m direction (16)
    const int bm = blockIdx.y * 128;
    const int bn = blockIdx.x * 128;

    float acc[8][8];
    #pragma unroll
    for (int i = 0; i < 8; ++i)
        #pragma unroll
        for (int j = 0; j < 8; ++j) acc[i][j] = 0.f;

    for (int k0 = 0; k0 < K; k0 += 16) {
        // Load A tile (128x16) transposed and B tile (16x128); 2 float4 each
        #pragma unroll
        for (int i = 0; i < 2; ++i) {
            int id = tid * 2 + i;                 // 0..511
            int ar = id >> 2, ac = (id & 3) << 2; // row 0..127, col {0,4,8,12}
            float4 a = *(const float4*)&A[(size_t)(bm + ar) * K + k0 + ac];
            As[ac + 0][ar] = a.x;
            As[ac + 1][ar] = a.y;
            As[ac + 2][ar] = a.z;
            As[ac + 3][ar] = a.w;
            int br = id >> 5, bc = (id & 31) << 2; // row 0..15, col 0..124
            *(float4*)&Bs[br][bc] = *(const float4*)&W[(size_t)(k0 + br) * N + bn + bc];
        }
        __syncthreads();

        #pragma unroll
        for (int kk = 0; kk < 16; ++kk) {
            float4 a0 = *(const float4*)&As[kk][ty * 8];
            float4 a1 = *(const float4*)&As[kk][ty * 8 + 4];
            float4 b0 = *(const float4*)&Bs[kk][tx * 8];
            float4 b1 = *(const float4*)&Bs[kk][tx * 8 + 4];
            float ra[8] = {a0.x, a0.y, a0.z, a0.w, a1.x, a1.y, a1.z, a1.w};
            float rb[8] = {b0.x, b0.y, b0.z, b0.w, b1.x, b1.y, b1.z, b1.w};
            #pragma unroll
            for (int i = 0; i < 8; ++i)
                #pragma unroll
                for (int j = 0; j < 8; ++j)
                    acc[i][j] = fmaf(ra[i], rb[j], acc[i][j]);
        }
        __syncthreads();
    }

    #pragma unroll
    for (int i = 0; i < 8; ++i) {
        int row = bm + ty * 8 + i;
        #pragma unroll
        for (int j = 0; j < 8; j += 4) {
            int col = bn + tx * 8 + j;
            float4 v = make_float4(acc[i][j], acc[i][j + 1], acc[i][j + 2], acc[i][j + 3]);
            if (BIAS) {
                v.x += bias[col]; v.y += bias[col + 1];
                v.z += bias[col + 2]; v.w += bias[col + 3];
            }
            *(float4*)&Cout[(size_t)row * N + col] = v;
        }
    }
}

// ----------------------------------------------------------------------------
// Causal flash attention (fp32, online softmax). BM=BN=64, D=64.
// grid: (T/64, B*H), 256 threads; each thread owns 4x4 of S and 4 rows x 4 dims of O.
// ----------------------------------------------------------------------------
__global__ __launch_bounds__(256, 2)
void attn_kernel(const float* __restrict__ qkv, float* __restrict__ ctx)
{
    extern __shared__ float sm[];
    float* Qt = sm;              // [d][m] 64x64 (Q pre-scaled by D^-0.5)
    float* Kt = Qt + 64 * 64;    // [d][n] 64x64
    float* Vs = Kt + 64 * 64;    // [n][d] 64x64
    float* Pt = Vs + 64 * 64;    // [n][m] 64x65 (padded)

    const int tid = threadIdx.x;
    const int tx = tid & 15;   // n / dim direction
    const int ty = tid >> 4;   // m direction
    const int bh = blockIdx.y;
    const int b = bh / HH, h = bh % HH;
    const int m0 = blockIdx.x * 64;

    const size_t rs = 3 * CC;  // row stride in qkv
    const float* qbase = qkv + (size_t)b * TT * rs + h * DD;
    const float* kbase = qbase + CC;
    const float* vbase = qbase + 2 * CC;
    const float scale = 0.125f;  // D^-0.5 for D=64

    // Load Q tile transposed, pre-scaled
    #pragma unroll
    for (int t4 = 0; t4 < 4; ++t4) {
        int i = tid + t4 * 256;              // float4 id 0..1023
        int r = i >> 4, c4 = (i & 15) << 2;  // row 0..63, col {0..60}
        float4 q = *(const float4*)&qbase[(size_t)(m0 + r) * rs + c4];
        Qt[(c4 + 0) * 64 + r] = q.x * scale;
        Qt[(c4 + 1) * 64 + r] = q.y * scale;
        Qt[(c4 + 2) * 64 + r] = q.z * scale;
        Qt[(c4 + 3) * 64 + r] = q.w * scale;
    }

    float o[4][4];
    float mi[4], li[4];
    #pragma unroll
    for (int i = 0; i < 4; ++i) {
        mi[i] = -1e30f; li[i] = 0.f;
        #pragma unroll
        for (int j = 0; j < 4; ++j) o[i][j] = 0.f;
    }

    const int ntiles = m0 / 64 + 1;  // causal: only tiles with n0 <= m0
    for (int it = 0; it < ntiles; ++it) {
        const int n0 = it * 64;
        __syncthreads();  // previous iter done with Kt/Vs (and Qt after load on it==0)

        // Load K tile transposed + V tile natural
        #pragma unroll
        for (int t4 = 0; t4 < 4; ++t4) {
            int i = tid + t4 * 256;
            int r = i >> 4, c4 = (i & 15) << 2;
            float4 k = *(const float4*)&kbase[(size_t)(n0 + r) * rs + c4];
            Kt[(c4 + 0) * 64 + r] = k.x;
            Kt[(c4 + 1) * 64 + r] = k.y;
            Kt[(c4 + 2) * 64 + r] = k.z;
            Kt[(c4 + 3) * 64 + r] = k.w;
            float4 v = *(const float4*)&vbase[(size_t)(n0 + r) * rs + c4];
            *(float4*)&Vs[r * 64 + c4] = v;
        }
        __syncthreads();

        // S = Q K^T (4x4 micro)
        float s[4][4];
        #pragma unroll
        for (int i = 0; i < 4; ++i)
            #pragma unroll
            for (int j = 0; j < 4; ++j) s[i][j] = 0.f;

        #pragma unroll 4
        for (int d = 0; d < 64; ++d) {
            float4 qa = *(const float4*)&Qt[d * 64 + ty * 4];
            float4 kb = *(const float4*)&Kt[d * 64 + tx * 4];
            float ra[4] = {qa.x, qa.y, qa.z, qa.w};
            float rb[4] = {kb.x, kb.y, kb.z, kb.w};
            #pragma unroll
            for (int i = 0; i < 4; ++i)
                #pragma unroll
                for (int j = 0; j < 4; ++j)
                    s[i][j] = fmaf(ra[i], rb[j], s[i][j]);
        }

        // Causal mask (only diagonal tile is partial)
        if (n0 == m0) {
            #pragma unroll
            for (int i = 0; i < 4; ++i)
                #pragma unroll
                for (int j = 0; j < 4; ++j)
                    if (tx * 4 + j > ty * 4 + i) s[i][j] = -1e30f;
        }

        // Online softmax per row; row group = 16 consecutive lanes (half warp)
        #pragma unroll
        for (int mm = 0; mm < 4; ++mm) {
            float mx = fmaxf(fmaxf(s[mm][0], s[mm][1]), fmaxf(s[mm][2], s[mm][3]));
            #pragma unroll
            for (int off = 1; off < 16; off <<= 1)
                mx = fmaxf(mx, __shfl_xor_sync(0xffffffffu, mx, off));
            float mnew = fmaxf(mi[mm], mx);
            float alpha = __expf(mi[mm] - mnew);
            mi[mm] = mnew;
            float rsum = 0.f;
            #pragma unroll
            for (int nn = 0; nn < 4; ++nn) {
                float p = __expf(s[mm][nn] - mnew);
                s[mm][nn] = p;
                rsum += p;
            }
            #pragma unroll
            for (int off = 1; off < 16; off <<= 1)
                rsum += __shfl_xor_sync(0xffffffffu, rsum, off);
            li[mm] = li[mm] * alpha + rsum;
            #pragma unroll
            for (int dd = 0; dd < 4; ++dd) o[mm][dd] *= alpha;
        }

        // Write P transposed [n][m] (pad 65 to break conflicts)
        #pragma unroll
        for (int mm = 0; mm < 4; ++mm)
            #pragma unroll
            for (int nn = 0; nn < 4; ++nn)
                Pt[(tx * 4 + nn) * 65 + ty * 4 + mm] = s[mm][nn];
        __syncthreads();

        // O += P @ V
        #pragma unroll 4
        for (int n = 0; n < 64; ++n) {
            float rp[4];
            #pragma unroll
            for (int mm = 0; mm < 4; ++mm) rp[mm] = Pt[n * 65 + ty * 4 + mm];
            float4 vv = *(const float4*)&Vs[n * 64 + tx * 4];
            float rv[4] = {vv.x, vv.y, vv.z, vv.w};
            #pragma unroll
            for (int mm = 0; mm < 4; ++mm)
                #pragma unroll
                for (int dd = 0; dd < 4; ++dd)
                    o[mm][dd] = fmaf(rp[mm], rv[dd], o[mm][dd]);
        }
    }

    // Normalize and write to ctx [B,T,C] at column h*D
    #pragma unroll
    for (int mm = 0; mm < 4; ++mm) {
        float inv = 1.f / li[mm];
        int t = m0 + ty * 4 + mm;
        float4 v = make_float4(o[mm][0] * inv, o[mm][1] * inv, o[mm][2] * inv, o[mm][3] * inv);
        *(float4*)&ctx[(size_t)b * TT * CC + (size_t)t * CC + h * DD + tx * 4] = v;
    }
}

// ----------------------------------------------------------------------------
extern "C" void kernel_launch(void* const* d_in, const int* in_sizes, int n_in,
                              void* d_out, int out_size)
{
    const float* x     = (const float*)d_in[0];  // [B,T,C]
    const float* w_qkv = (const float*)d_in[1];  // [C,3C]
    const float* w_out = (const float*)d_in[2];  // [C,C]
    const float* b_out = (const float*)d_in[3];  // [C]
    float* out = (float*)d_out;                  // [B,T,C]

    float *qkv = nullptr, *ctx = nullptr;
    cudaGetSymbolAddress((void**)&qkv, g_qkv);
    cudaGetSymbolAddress((void**)&ctx, g_ctx);

    const int M = BB * TT;       // 8192
    const int smem_attn = (3 * 64 * 64 + 64 * 65) * (int)sizeof(float);  // 65792 B

    static bool attr_set = false;
    if (!attr_set) {
        cudaFuncSetAttribute(attn_kernel, cudaFuncAttributeMaxDynamicSharedMemorySize, smem_attn);
        attr_set = true;
    }

    // 1) QKV = x @ w_qkv   [8192,1024]x[1024,3072]
    sgemm128<false><<<dim3(3 * CC / 128, M / 128), 256>>>(x, w_qkv, nullptr, qkv, M, 3 * CC, CC);

    // 2) causal flash attention -> ctx [B,T,C]
    attn_kernel<<<dim3(TT / 64, BB * HH), 256, smem_attn>>>(qkv, ctx);

    // 3) out = ctx @ w_out + b_out   [8192,1024]x[1024,1024]
    sgemm128<true><<<dim3(CC / 128, M / 128), 256>>>(ctx, w_out, b_out, out, M, CC, CC);
}

// round 2
// speedup vs baseline: 1.4770x; 1.4770x over previous
#include <cuda_runtime.h>
#include <cuda_bf16.h>
#include <math.h>

// Problem constants
#define BB 4
#define TT 2048
#define CC 1024
#define HH 16
#define DD 64
// M = BB*TT = 8192

// Scratch (allocation-free rule: __device__ globals)
__device__ float g_qkv[(size_t)BB * TT * 3 * CC];  // [B,T,3C]
__device__ float g_ctx[(size_t)BB * TT * CC];      // [B,T,C]

// ----------------------------------------------------------------------------
// Tensor-core GEMM with bf16x3 error compensation.
// C[M,N] = A[M,K] @ W[K,N] (+bias), fp32 in/out, ~fp32 accuracy.
// Block tile 128x128, BK=16, 256 threads (8 warps; 4 in M x 2 in N).
// Warp tile 32x64 = 2 m16 x 8 n8 mma tiles. 3 MMAs per logical tile (hi*hi,
// hi*lo, lo*hi). Double-buffered smem, ldmatrix fragment loads.
// Smem rows padded to 24 bf16 (48B): 16B-aligned + conflict-free ldmatrix.
// ----------------------------------------------------------------------------
#define SSTRIDE 24

__device__ __forceinline__ void mma_bf16(float* c, const unsigned* a,
                                         unsigned b0, unsigned b1) {
    asm volatile(
        "mma.sync.aligned.m16n8k16.row.col.f32.bf16.bf16.f32 "
        "{%0,%1,%2,%3}, {%4,%5,%6,%7}, {%8,%9}, {%0,%1,%2,%3};"
        : "+f"(c[0]), "+f"(c[1]), "+f"(c[2]), "+f"(c[3])
        : "r"(a[0]), "r"(a[1]), "r"(a[2]), "r"(a[3]), "r"(b0), "r"(b1));
}

__device__ __forceinline__ void ldsm4(unsigned* r, const __nv_bfloat16* p) {
    unsigned addr = (unsigned)__cvta_generic_to_shared(p);
    asm volatile("ldmatrix.sync.aligned.m8n8.x4.shared.b16 {%0,%1,%2,%3}, [%4];"
                 : "=r"(r[0]), "=r"(r[1]), "=r"(r[2]), "=r"(r[3]) : "r"(addr));
}

template <bool BIAS>
__global__ __launch_bounds__(256, 2)
void gemm_tc(const float* __restrict__ A, const float* __restrict__ W,
             const float* __restrict__ bias, float* __restrict__ Cout,
             int M, int N, int K)
{
    // [buf][term(hi=0,lo=1)][row * SSTRIDE + k]
    __shared__ __nv_bfloat16 As[2][2][128 * SSTRIDE];
    __shared__ __nv_bfloat16 Bs[2][2][128 * SSTRIDE];  // B stored [n][k]

    const int tid = threadIdx.x;
    const int warp = tid >> 5, lane = tid & 31;
    const int wm = warp & 3, wn = warp >> 2;
    const int bm = blockIdx.y * 128, bn = blockIdx.x * 128;

    float acc[2][8][4];
    #pragma unroll
    for (int i = 0; i < 2; ++i)
        #pragma unroll
        for (int j = 0; j < 8; ++j)
            #pragma unroll
            for (int q = 0; q < 4; ++q) acc[i][j][q] = 0.f;

    // Staging registers for the double-buffer pipeline
    float4 ra[2];      // A: 128x16 tile, thread owns 2 float4 along K
    float  rbv[8];     // B: 16x128 tile, thread owns column n, 8 k-values
    const int a_row0 = tid >> 1;              // rows 0..127 (2 threads/row)
    const int a_c0 = (tid & 1) << 3;          // k offset 0 or 8
    const int b_n = tid & 127;                // column n 0..127
    const int b_k0 = (tid >> 7) << 3;         // k offset 0 or 8

    auto gload = [&](int k0) {
        ra[0] = *(const float4*)&A[(size_t)(bm + a_row0) * K + k0 + a_c0];
        ra[1] = *(const float4*)&A[(size_t)(bm + a_row0) * K + k0 + a_c0 + 4];
        #pragma unroll
        for (int q = 0; q < 8; ++q)
            rbv[q] = W[(size_t)(k0 + b_k0 + q) * N + bn + b_n];
    };

    auto sstore = [&](int buf) {
        // A: 8 consecutive k values -> hi/lo bf16 pairs
        float av[8] = {ra[0].x, ra[0].y, ra[0].z, ra[0].w,
                       ra[1].x, ra[1].y, ra[1].z, ra[1].w};
        #pragma unroll
        for (int q = 0; q < 8; q += 2) {
            __nv_bfloat16 h0 = __float2bfloat16(av[q]);
            __nv_bfloat16 h1 = __float2bfloat16(av[q + 1]);
            __nv_bfloat16 l0 = __float2bfloat16(av[q] - __bfloat162float(h0));
            __nv_bfloat16 l1 = __float2bfloat16(av[q + 1] - __bfloat162float(h1));
            __nv_bfloat162 hp; hp.x = h0; hp.y = h1;
            __nv_bfloat162 lp; lp.x = l0; lp.y = l1;
            *(__nv_bfloat162*)&As[buf][0][a_row0 * SSTRIDE + a_c0 + q] = hp;
            *(__nv_bfloat162*)&As[buf][1][a_row0 * SSTRIDE + a_c0 + q] = lp;
        }
        // B transposed: thread owns Bs[n][k0..k0+7] contiguous
        #pragma unroll
        for (int q = 0; q < 8; q += 2) {
            __nv_bfloat16 h0 = __float2bfloat16(rbv[q]);
            __nv_bfloat16 h1 = __float2bfloat16(rbv[q + 1]);
            __nv_bfloat16 l0 = __float2bfloat16(rbv[q] - __bfloat162float(h0));
            __nv_bfloat16 l1 = __float2bfloat16(rbv[q + 1] - __bfloat162float(h1));
            __nv_bfloat162 hp; hp.x = h0; hp.y = h1;
            __nv_bfloat162 lp; lp.x = l0; lp.y = l1;
            *(__nv_bfloat162*)&Bs[buf][0][b_n * SSTRIDE + b_k0 + q] = hp;
            *(__nv_bfloat162*)&Bs[buf][1][b_n * SSTRIDE + b_k0 + q] = lp;
        }
    };

    auto compute = [&](int buf) {
        // A fragments: 2 m16 tiles x 2 terms
        unsigned af[2][2][4];
        const int ar = wm * 32 + (lane & 15);
        const int akh = (lane >> 4) << 3;
        #pragma unroll
        for (int i = 0; i < 2; ++i)
            #pragma unroll
            for (int t = 0; t < 2; ++t)
                ldsm4(af[i][t], &As[buf][t][(ar + i * 16) * SSTRIDE + akh]);

        // B fragments in pairs of n8 tiles; 4 pairs cover n 0..63
        const int br = wn * 64 + ((lane >> 4) << 3) + (lane & 7);
        const int bkh = ((lane >> 3) & 1) << 3;
        #pragma unroll
        for (int p = 0; p < 4; ++p) {
            unsigned bf[2][4];
            #pragma unroll
            for (int t = 0; t < 2; ++t)
                ldsm4(bf[t], &Bs[buf][t][(br + p * 16) * SSTRIDE + bkh]);
            #pragma unroll
            for (int i = 0; i < 2; ++i)
                #pragma unroll
                for (int jj = 0; jj < 2; ++jj) {
                    float* c = acc[i][2 * p + jj];
                    mma_bf16(c, af[i][0], bf[0][jj * 2], bf[0][jj * 2 + 1]); // hi*hi
                    mma_bf16(c, af[i][0], bf[1][jj * 2], bf[1][jj * 2 + 1]); // hi*lo
                    mma_bf16(c, af[i][1], bf[0][jj * 2], bf[0][jj * 2 + 1]); // lo*hi
                }
        }
    };

    const int iters = K >> 4;
    gload(0);
    sstore(0);
    for (int it = 0; it < iters; ++it) {
        __syncthreads();
        if (it + 1 < iters) gload((it + 1) << 4);
        compute(it & 1);
        if (it + 1 < iters) sstore((it + 1) & 1);
    }

    // Epilogue
    const int g = lane >> 2, tg = lane & 3;
    #pragma unroll
    for (int i = 0; i < 2; ++i) {
        int row0 = bm + wm * 32 + i * 16 + g;
        #pragma unroll
        for (int j = 0; j < 8; ++j) {
            int col = bn + wn * 64 + j * 8 + 2 * tg;
            float b0 = 0.f, b1 = 0.f;
            if (BIAS) { b0 = bias[col]; b1 = bias[col + 1]; }
            float2 v0 = make_float2(acc[i][j][0] + b0, acc[i][j][1] + b1);
            float2 v1 = make_float2(acc[i][j][2] + b0, acc[i][j][3] + b1);
            *(float2*)&Cout[(size_t)row0 * N + col] = v0;
            *(float2*)&Cout[(size_t)(row0 + 8) * N + col] = v1;
        }
    }
}

// ----------------------------------------------------------------------------
// Causal flash attention (fp32, online softmax). BM=BN=64, D=64. (unchanged R1)
// ----------------------------------------------------------------------------
__global__ __launch_bounds__(256, 2)
void attn_kernel(const float* __restrict__ qkv, float* __restrict__ ctx)
{
    extern __shared__ float sm[];
    float* Qt = sm;              // [d][m] 64x64 (Q pre-scaled)
    float* Kt = Qt + 64 * 64;    // [d][n]
    float* Vs = Kt + 64 * 64;    // [n][d]
    float* Pt = Vs + 64 * 64;    // [n][m] 64x65

    const int tid = threadIdx.x;
    const int tx = tid & 15;
    const int ty = tid >> 4;
    const int bh = blockIdx.y;
    const int b = bh / HH, h = bh % HH;
    const int m0 = blockIdx.x * 64;

    const size_t rs = 3 * CC;
    const float* qbase = qkv + (size_t)b * TT * rs + h * DD;
    const float* kbase = qbase + CC;
    const float* vbase = qbase + 2 * CC;
    const float scale = 0.125f;

    #pragma unroll
    for (int t4 = 0; t4 < 4; ++t4) {
        int i = tid + t4 * 256;
        int r = i >> 4, c4 = (i & 15) << 2;
        float4 q = *(const float4*)&qbase[(size_t)(m0 + r) * rs + c4];
        Qt[(c4 + 0) * 64 + r] = q.x * scale;
        Qt[(c4 + 1) * 64 + r] = q.y * scale;
        Qt[(c4 + 2) * 64 + r] = q.z * scale;
        Qt[(c4 + 3) * 64 + r] = q.w * scale;
    }

    float o[4][4];
    float mi[4], li[4];
    #pragma unroll
    for (int i = 0; i < 4; ++i) {
        mi[i] = -1e30f; li[i] = 0.f;
        #pragma unroll
        for (int j = 0; j < 4; ++j) o[i][j] = 0.f;
    }

    const int ntiles = m0 / 64 + 1;
    for (int it = 0; it < ntiles; ++it) {
        const int n0 = it * 64;
        __syncthreads();

        #pragma unroll
        for (int t4 = 0; t4 < 4; ++t4) {
            int i = tid + t4 * 256;
            int r = i >> 4, c4 = (i & 15) << 2;
            float4 k = *(const float4*)&kbase[(size_t)(n0 + r) * rs + c4];
            Kt[(c4 + 0) * 64 + r] = k.x;
            Kt[(c4 + 1) * 64 + r] = k.y;
            Kt[(c4 + 2) * 64 + r] = k.z;
            Kt[(c4 + 3) * 64 + r] = k.w;
            float4 v = *(const float4*)&vbase[(size_t)(n0 + r) * rs + c4];
            *(float4*)&Vs[r * 64 + c4] = v;
        }
        __syncthreads();

        float s[4][4];
        #pragma unroll
        for (int i = 0; i < 4; ++i)
            #pragma unroll
            for (int j = 0; j < 4; ++j) s[i][j] = 0.f;

        #pragma unroll 4
        for (int d = 0; d < 64; ++d) {
            float4 qa = *(const float4*)&Qt[d * 64 + ty * 4];
            float4 kb = *(const float4*)&Kt[d * 64 + tx * 4];
            float raa[4] = {qa.x, qa.y, qa.z, qa.w};
            float rbb[4] = {kb.x, kb.y, kb.z, kb.w};
            #pragma unroll
            for (int i = 0; i < 4; ++i)
                #pragma unroll
                for (int j = 0; j < 4; ++j)
                    s[i][j] = fmaf(raa[i], rbb[j], s[i][j]);
        }

        if (n0 == m0) {
            #pragma unroll
            for (int i = 0; i < 4; ++i)
                #pragma unroll
                for (int j = 0; j < 4; ++j)
                    if (tx * 4 + j > ty * 4 + i) s[i][j] = -1e30f;
        }

        #pragma unroll
        for (int mm = 0; mm < 4; ++mm) {
            float mx = fmaxf(fmaxf(s[mm][0], s[mm][1]), fmaxf(s[mm][2], s[mm][3]));
            #pragma unroll
            for (int off = 1; off < 16; off <<= 1)
                mx = fmaxf(mx, __shfl_xor_sync(0xffffffffu, mx, off));
            float mnew = fmaxf(mi[mm], mx);
            float alpha = __expf(mi[mm] - mnew);
            mi[mm] = mnew;
            float rsum = 0.f;
            #pragma unroll
            for (int nn = 0; nn < 4; ++nn) {
                float p = __expf(s[mm][nn] - mnew);
                s[mm][nn] = p;
                rsum += p;
            }
            #pragma unroll
            for (int off = 1; off < 16; off <<= 1)
                rsum += __shfl_xor_sync(0xffffffffu, rsum, off);
            li[mm] = li[mm] * alpha + rsum;
            #pragma unroll
            for (int dd = 0; dd < 4; ++dd) o[mm][dd] *= alpha;
        }

        #pragma unroll
        for (int mm = 0; mm < 4; ++mm)
            #pragma unroll
            for (int nn = 0; nn < 4; ++nn)
                Pt[(tx * 4 + nn) * 65 + ty * 4 + mm] = s[mm][nn];
        __syncthreads();

        #pragma unroll 4
        for (int n = 0; n < 64; ++n) {
            float rp[4];
            #pragma unroll
            for (int mm = 0; mm < 4; ++mm) rp[mm] = Pt[n * 65 + ty * 4 + mm];
            float4 vv = *(const float4*)&Vs[n * 64 + tx * 4];
            float rv[4] = {vv.x, vv.y, vv.z, vv.w};
            #pragma unroll
            for (int mm = 0; mm < 4; ++mm)
                #pragma unroll
                for (int dd = 0; dd < 4; ++dd)
                    o[mm][dd] = fmaf(rp[mm], rv[dd], o[mm][dd]);
        }
    }

    #pragma unroll
    for (int mm = 0; mm < 4; ++mm) {
        float inv = 1.f / li[mm];
        int t = m0 + ty * 4 + mm;
        float4 v = make_float4(o[mm][0] * inv, o[mm][1] * inv, o[mm][2] * inv, o[mm][3] * inv);
        *(float4*)&ctx[(size_t)b * TT * CC + (size_t)t * CC + h * DD + tx * 4] = v;
    }
}

// ----------------------------------------------------------------------------
extern "C" void kernel_launch(void* const* d_in, const int* in_sizes, int n_in,
                              void* d_out, int out_size)
{
    const float* x     = (const float*)d_in[0];
    const float* w_qkv = (const float*)d_in[1];
    const float* w_out = (const float*)d_in[2];
    const float* b_out = (const float*)d_in[3];
    float* out = (float*)d_out;

    float *qkv = nullptr, *ctx = nullptr;
    cudaGetSymbolAddress((void**)&qkv, g_qkv);
    cudaGetSymbolAddress((void**)&ctx, g_ctx);

    const int M = BB * TT;
    const int smem_attn = (3 * 64 * 64 + 64 * 65) * (int)sizeof(float);

    static bool attr_set = false;
    if (!attr_set) {
        cudaFuncSetAttribute(attn_kernel, cudaFuncAttributeMaxDynamicSharedMemorySize, smem_attn);
        attr_set = true;
    }

    // 1) QKV = x @ w_qkv
    gemm_tc<false><<<dim3(3 * CC / 128, M / 128), 256>>>(x, w_qkv, nullptr, qkv, M, 3 * CC, CC);

    // 2) causal flash attention
    attn_kernel<<<dim3(TT / 64, BB * HH), 256, smem_attn>>>(qkv, ctx);

    // 3) out = ctx @ w_out + b_out
    gemm_tc<true><<<dim3(CC / 128, M / 128), 256>>>(ctx, w_out, b_out, out, M, CC, CC);
}

// round 3
// speedup vs baseline: 3.1920x; 2.1610x over previous
#include <cuda_runtime.h>
#include <cuda_bf16.h>
#include <math.h>

#define BB 4
#define TT 2048
#define CC 1024
#define HH 16
#define DD 64
// M = BB*TT = 8192

// ---------------- scratch (device globals; no allocations) ------------------
__device__ __nv_bfloat16 g_xh[(size_t)BB * TT * CC];
__device__ __nv_bfloat16 g_xl[(size_t)BB * TT * CC];
__device__ __nv_bfloat16 g_wqh[(size_t)CC * 3 * CC];
__device__ __nv_bfloat16 g_wql[(size_t)CC * 3 * CC];
__device__ __nv_bfloat16 g_woh[(size_t)CC * CC];
__device__ __nv_bfloat16 g_wol[(size_t)CC * CC];
__device__ __nv_bfloat16 g_qkvh[(size_t)BB * TT * 3 * CC];
__device__ __nv_bfloat16 g_qkvl[(size_t)BB * TT * 3 * CC];
__device__ __nv_bfloat16 g_ctxh[(size_t)BB * TT * CC];
__device__ __nv_bfloat16 g_ctxl[(size_t)BB * TT * CC];

// ---------------- helpers ----------------------------------------------------
__device__ __forceinline__ unsigned pk2(float lo, float hi) {
    unsigned r;
    asm("cvt.rn.bf16x2.f32 %0, %1, %2;" : "=r"(r) : "f"(hi), "f"(lo));
    return r;
}
__device__ __forceinline__ void split_pk(float x0, float x1, unsigned& h, unsigned& l) {
    h = pk2(x0, x1);
    float h0 = __int_as_float(h << 16);
    float h1 = __int_as_float(h & 0xFFFF0000u);
    l = pk2(x0 - h0, x1 - h1);
}
__device__ __forceinline__ void mma_bf16(float* c, const unsigned* a,
                                         unsigned b0, unsigned b1) {
    asm volatile(
        "mma.sync.aligned.m16n8k16.row.col.f32.bf16.bf16.f32 "
        "{%0,%1,%2,%3}, {%4,%5,%6,%7}, {%8,%9}, {%0,%1,%2,%3};"
        : "+f"(c[0]), "+f"(c[1]), "+f"(c[2]), "+f"(c[3])
        : "r"(a[0]), "r"(a[1]), "r"(a[2]), "r"(a[3]), "r"(b0), "r"(b1));
}
__device__ __forceinline__ void ldsm4(unsigned* r, const __nv_bfloat16* p) {
    unsigned a = (unsigned)__cvta_generic_to_shared(p);
    asm volatile("ldmatrix.sync.aligned.m8n8.x4.shared.b16 {%0,%1,%2,%3}, [%4];"
                 : "=r"(r[0]), "=r"(r[1]), "=r"(r[2]), "=r"(r[3]) : "r"(a));
}
__device__ __forceinline__ void ldsm4t(unsigned* r, const __nv_bfloat16* p) {
    unsigned a = (unsigned)__cvta_generic_to_shared(p);
    asm volatile("ldmatrix.sync.aligned.m8n8.x4.trans.shared.b16 {%0,%1,%2,%3}, [%4];"
                 : "=r"(r[0]), "=r"(r[1]), "=r"(r[2]), "=r"(r[3]) : "r"(a));
}
__device__ __forceinline__ void cp16(const __nv_bfloat16* smem_dst, const __nv_bfloat16* gsrc) {
    unsigned d = (unsigned)__cvta_generic_to_shared(smem_dst);
    asm volatile("cp.async.ca.shared.global [%0], [%1], 16;" :: "r"(d), "l"(gsrc));
}
__device__ __forceinline__ void cp_commit() { asm volatile("cp.async.commit_group;"); }

// exp2 via magic-round + deg-6 Taylor (pure FMA/ALU pipe, no MUFU)
__device__ __forceinline__ float exp2p(float p) {
    p = fmaxf(p, -120.f);
    float t = p + 12582912.f;           // 2^23 + 2^22
    int ii = __float_as_int(t) - 0x4B400000;
    float f = p - (t - 12582912.f);     // f in [-0.5, 0.5]
    float r = 1.5403530e-4f;
    r = fmaf(r, f, 1.3333558e-3f);
    r = fmaf(r, f, 9.6181291e-3f);
    r = fmaf(r, f, 5.5504109e-2f);
    r = fmaf(r, f, 2.4022651e-1f);
    r = fmaf(r, f, 6.9314718e-1f);
    r = fmaf(r, f, 1.0f);
    return r * __int_as_float((ii + 127) << 23);
}

// ---------------- input split kernel -----------------------------------------
__global__ void split_kernel(const float2* __restrict__ src,
                             unsigned* __restrict__ hi, unsigned* __restrict__ lo, int n2)
{
    int i = blockIdx.x * blockDim.x + threadIdx.x;
    if (i < n2) {
        float2 v = src[i];
        unsigned h, l;
        split_pk(v.x, v.y, h, l);
        hi[i] = h; lo[i] = l;
    }
}

// ---------------- GEMM on split bf16 inputs -----------------------------------
// C = A @ B, A=[M,K] (hi/lo planes), B=[K,N] (hi/lo). BM=BN=128, BK=32, 256 thr.
// smem: As[m][k] stride 40, Bs[k][n] stride 136, double-buffered, cp.async.
#define GEMM_SMEM 75776
template <bool SPLIT_OUT, bool BIAS>
__global__ __launch_bounds__(256, 2)
void gemm_sp(const __nv_bfloat16* __restrict__ Ah, const __nv_bfloat16* __restrict__ Al,
             const __nv_bfloat16* __restrict__ Bh, const __nv_bfloat16* __restrict__ Bl,
             float* __restrict__ Cf, __nv_bfloat16* __restrict__ Ch,
             __nv_bfloat16* __restrict__ Cl, const float* __restrict__ bias,
             int M, int N, int K, float qscale, int qcols)
{
    extern __shared__ __nv_bfloat16 sm[];
    const int tid = threadIdx.x, warp = tid >> 5, lane = tid & 31;
    const int wm = warp & 3, wn = warp >> 2;
    const int bm = blockIdx.y * 128, bn = blockIdx.x * 128;

    // layout: per buf: A(2 terms x 128*40=5120) then B(2 terms x 32*136=4352)
    auto As = [&](int buf, int t) { return sm + buf * 18944 + t * 5120; };
    auto Bs = [&](int buf, int t) { return sm + buf * 18944 + 10240 + t * 4352; };

    float acc[2][8][4];
    #pragma unroll
    for (int i = 0; i < 2; ++i)
        #pragma unroll
        for (int j = 0; j < 8; ++j)
            #pragma unroll
            for (int q = 0; q < 4; ++q) acc[i][j][q] = 0.f;

    auto loadbuf = [&](int buf, int k0) {
        #pragma unroll
        for (int t = 0; t < 2; ++t) {
            const __nv_bfloat16* Ag = t ? Al : Ah;
            #pragma unroll
            for (int c = 0; c < 2; ++c) {
                int id = tid + c * 256;            // 0..511
                int row = id >> 2, col8 = (id & 3) << 3;
                cp16(As(buf, t) + row * 40 + col8,
                     Ag + (size_t)(bm + row) * K + k0 + col8);
            }
            const __nv_bfloat16* Bg = t ? Bl : Bh;
            #pragma unroll
            for (int c = 0; c < 2; ++c) {
                int id = tid + c * 256;
                int row = id >> 4, col8 = (id & 15) << 3;
                cp16(Bs(buf, t) + row * 136 + col8,
                     Bg + (size_t)(k0 + row) * N + bn + col8);
            }
        }
    };

    const int iters = K >> 5;
    loadbuf(0, 0);
    cp_commit();

    for (int it = 0; it < iters; ++it) {
        if (it + 1 < iters) {
            loadbuf((it + 1) & 1, (it + 1) << 5);
            cp_commit();
            asm volatile("cp.async.wait_group 1;");
        } else {
            asm volatile("cp.async.wait_group 0;");
        }
        __syncthreads();
        const int buf = it & 1;

        #pragma unroll
        for (int kk = 0; kk < 2; ++kk) {
            unsigned af[2][2][4];  // [m16 i][term]
            #pragma unroll
            for (int i = 0; i < 2; ++i)
                #pragma unroll
                for (int t = 0; t < 2; ++t)
                    ldsm4(af[i][t], As(buf, t) +
                          (wm * 32 + i * 16 + (lane & 15)) * 40 + kk * 16 + ((lane >> 4) << 3));
            #pragma unroll
            for (int p = 0; p < 4; ++p) {
                unsigned bh_[4], bl_[4];
                const __nv_bfloat16* bp0 = Bs(buf, 0) +
                    (kk * 16 + (lane & 15)) * 136 + wn * 64 + p * 16 + ((lane >> 4) << 3);
                const __nv_bfloat16* bp1 = Bs(buf, 1) +
                    (kk * 16 + (lane & 15)) * 136 + wn * 64 + p * 16 + ((lane >> 4) << 3);
                ldsm4t(bh_, bp0);
                ldsm4t(bl_, bp1);
                #pragma unroll
                for (int i = 0; i < 2; ++i)
                    #pragma unroll
                    for (int jj = 0; jj < 2; ++jj) {
                        float* c = acc[i][2 * p + jj];
                        mma_bf16(c, af[i][0], bh_[2 * jj], bh_[2 * jj + 1]);
                        mma_bf16(c, af[i][0], bl_[2 * jj], bl_[2 * jj + 1]);
                        mma_bf16(c, af[i][1], bh_[2 * jj], bh_[2 * jj + 1]);
                    }
            }
        }
        __syncthreads();
    }

    // epilogue
    const int g = lane >> 2, tg = lane & 3;
    #pragma unroll
    for (int i = 0; i < 2; ++i) {
        int row0 = bm + wm * 32 + i * 16 + g;
        #pragma unroll
        for (int j = 0; j < 8; ++j) {
            int col = bn + wn * 64 + j * 8 + 2 * tg;
            float v0 = acc[i][j][0], v1 = acc[i][j][1];
            float v2 = acc[i][j][2], v3 = acc[i][j][3];
            if (SPLIT_OUT) {
                float fac = (col < qcols) ? qscale : 1.f;
                v0 *= fac; v1 *= fac; v2 *= fac; v3 *= fac;
                unsigned h, l;
                split_pk(v0, v1, h, l);
                *(unsigned*)(Ch + (size_t)row0 * N + col) = h;
                *(unsigned*)(Cl + (size_t)row0 * N + col) = l;
                split_pk(v2, v3, h, l);
                *(unsigned*)(Ch + (size_t)(row0 + 8) * N + col) = h;
                *(unsigned*)(Cl + (size_t)(row0 + 8) * N + col) = l;
            } else {
                float b0 = 0.f, b1 = 0.f;
                if (BIAS) { b0 = bias[col]; b1 = bias[col + 1]; }
                float2 w0 = make_float2(v0 + b0, v1 + b1);
                float2 w1 = make_float2(v2 + b0, v3 + b1);
                *(float2*)&Cf[(size_t)row0 * N + col] = w0;
                *(float2*)&Cf[(size_t)(row0 + 8) * N + col] = w1;
            }
        }
    }
}

// ---------------- tensor-core causal flash attention ---------------------------
// BM=128 (8 warps x 16 rows), BN=64 keys/iter, D=64. Q/K/V hi+lo bf16 (x3 MMA).
// Softmax in log2 domain (Q pre-scaled by 0.125*log2e in qkv epilogue).
#define ATTN_SMEM 110592
__global__ __launch_bounds__(256, 1)
void attn_tc(const __nv_bfloat16* __restrict__ qh, const __nv_bfloat16* __restrict__ ql,
             __nv_bfloat16* __restrict__ ch, __nv_bfloat16* __restrict__ cl)
{
    extern __shared__ __nv_bfloat16 sm[];
    // Q: hi at 0, lo at 9216 (128 x 72). KV buf b at 18432 + b*18432:
    //   Kh +0, Kl +4608, Vh +9216, Vl +13824 (each 64 x 72)
    const int tid = threadIdx.x, warp = tid >> 5, lane = tid & 31;
    const int g = lane >> 2, tg = lane & 3;
    const int bh = blockIdx.y;
    const int b = bh / HH, h = bh % HH;
    const int m0 = blockIdx.x * 128;
    const size_t bt0 = (size_t)b * TT;
    const size_t rs = 3 * CC;
    const int colq = h * DD, colk = CC + h * DD, colv = 2 * CC + h * DD;

    auto load_kv = [&](int it, int buf) {
        const int n0 = it * 64;
        __nv_bfloat16* base = sm + 18432 + buf * 18432;
        const __nv_bfloat16* srcs[4] = {qh, ql, qh, ql};
        const int cols[4] = {colk, colk, colv, colv};
        #pragma unroll
        for (int pl = 0; pl < 4; ++pl) {
            #pragma unroll
            for (int c = 0; c < 2; ++c) {
                int id = tid + c * 256;           // 0..511
                int row = id >> 3, col8 = (id & 7) << 3;
                cp16(base + pl * 4608 + row * 72 + col8,
                     srcs[pl] + (bt0 + n0 + row) * rs + cols[pl] + col8);
            }
        }
    };

    // Q load (group 0 together with first KV tile)
    #pragma unroll
    for (int t = 0; t < 2; ++t) {
        const __nv_bfloat16* src = t ? ql : qh;
        #pragma unroll
        for (int c = 0; c < 4; ++c) {
            int id = tid + c * 256;               // 0..1023
            int row = id >> 3, col8 = (id & 7) << 3;
            cp16(sm + t * 9216 + row * 72 + col8,
                 src + (bt0 + m0 + row) * rs + colq + col8);
        }
    }
    load_kv(0, 0);
    cp_commit();

    unsigned qf[4][2][4];   // [k16][term]
    float o[8][4];
    float mrow[2] = {-1e30f, -1e30f}, lrow[2] = {0.f, 0.f};
    #pragma unroll
    for (int j = 0; j < 8; ++j)
        #pragma unroll
        for (int q = 0; q < 4; ++q) o[j][q] = 0.f;

    const int nt = (m0 >> 6) + 2;
    for (int it = 0; it < nt; ++it) {
        if (it + 1 < nt) {
            load_kv(it + 1, (it + 1) & 1);
            cp_commit();
            asm volatile("cp.async.wait_group 1;");
        } else {
            asm volatile("cp.async.wait_group 0;");
        }
        __syncthreads();

        if (it == 0) {
            #pragma unroll
            for (int kk = 0; kk < 4; ++kk)
                #pragma unroll
                for (int t = 0; t < 2; ++t)
                    ldsm4(qf[kk][t], sm + t * 9216 +
                          (warp * 16 + (lane & 15)) * 72 + kk * 16 + ((lane >> 4) << 3));
        }

        const int buf = it & 1;
        const __nv_bfloat16* Kh = sm + 18432 + buf * 18432;
        const __nv_bfloat16* Kl = Kh + 4608;
        const __nv_bfloat16* Vh = Kh + 9216;
        const __nv_bfloat16* Vl = Kh + 13824;
        const int n0 = it * 64;

        // S = Q K^T (log2 domain)
        float sc[8][4];
        #pragma unroll
        for (int j = 0; j < 8; ++j)
            #pragma unroll
            for (int q = 0; q < 4; ++q) sc[j][q] = 0.f;

        #pragma unroll
        for (int kk = 0; kk < 4; ++kk) {
            #pragma unroll
            for (int p = 0; p < 4; ++p) {
                const int krow = p * 16 + (lane & 7) + ((lane >> 4) << 3);
                const int kcol = kk * 16 + (((lane >> 3) & 1) << 3);
                unsigned kbh[4], kbl[4];
                ldsm4(kbh, Kh + krow * 72 + kcol);
                ldsm4(kbl, Kl + krow * 72 + kcol);
                #pragma unroll
                for (int jj = 0; jj < 2; ++jj) {
                    float* c = sc[2 * p + jj];
                    mma_bf16(c, qf[kk][0], kbh[2 * jj], kbh[2 * jj + 1]);
                    mma_bf16(c, qf[kk][0], kbl[2 * jj], kbl[2 * jj + 1]);
                    mma_bf16(c, qf[kk][1], kbh[2 * jj], kbh[2 * jj + 1]);
                }
            }
        }

        // causal mask (only possibly-partial tiles)
        const int r0 = m0 + warp * 16 + g, r1 = r0 + 8;
        if (n0 + 63 > m0) {
            #pragma unroll
            for (int j = 0; j < 8; ++j) {
                int cb = n0 + j * 8 + 2 * tg;
                if (cb > r0) sc[j][0] = -1e30f;
                if (cb + 1 > r0) sc[j][1] = -1e30f;
                if (cb > r1) sc[j][2] = -1e30f;
                if (cb + 1 > r1) sc[j][3] = -1e30f;
            }
        }

        // online softmax, base-2
        #pragma unroll
        for (int r = 0; r < 2; ++r) {
            float mx = -1e30f;
            #pragma unroll
            for (int j = 0; j < 8; ++j)
                mx = fmaxf(mx, fmaxf(sc[j][2 * r], sc[j][2 * r + 1]));
            mx = fmaxf(mx, __shfl_xor_sync(0xffffffffu, mx, 1));
            mx = fmaxf(mx, __shfl_xor_sync(0xffffffffu, mx, 2));
            float mnew = fmaxf(mrow[r], mx);
            float alpha = exp2p(mrow[r] - mnew);
            mrow[r] = mnew;
            float rsum = 0.f;
            #pragma unroll
            for (int j = 0; j < 8; ++j) {
                float p0 = exp2p(sc[j][2 * r] - mnew);
                float p1 = exp2p(sc[j][2 * r + 1] - mnew);
                sc[j][2 * r] = p0; sc[j][2 * r + 1] = p1;
                rsum += p0 + p1;
            }
            rsum += __shfl_xor_sync(0xffffffffu, rsum, 1);
            rsum += __shfl_xor_sync(0xffffffffu, rsum, 2);
            lrow[r] = lrow[r] * alpha + rsum;
            #pragma unroll
            for (int j = 0; j < 8; ++j) {
                o[j][2 * r] *= alpha;
                o[j][2 * r + 1] *= alpha;
            }
        }

        // O += P V (P split hi/lo in registers)
        #pragma unroll
        for (int s = 0; s < 4; ++s) {
            unsigned pah[4], pal[4];
            split_pk(sc[2 * s][0], sc[2 * s][1], pah[0], pal[0]);
            split_pk(sc[2 * s][2], sc[2 * s][3], pah[1], pal[1]);
            split_pk(sc[2 * s + 1][0], sc[2 * s + 1][1], pah[2], pal[2]);
            split_pk(sc[2 * s + 1][2], sc[2 * s + 1][3], pah[3], pal[3]);
            #pragma unroll
            for (int p = 0; p < 4; ++p) {
                const int vrow = s * 16 + (lane & 15);
                const int vcol = p * 16 + ((lane >> 4) << 3);
                unsigned vbh[4], vbl[4];
                ldsm4t(vbh, Vh + vrow * 72 + vcol);
                ldsm4t(vbl, Vl + vrow * 72 + vcol);
                #pragma unroll
                for (int jj = 0; jj < 2; ++jj) {
                    float* c = o[2 * p + jj];
                    mma_bf16(c, pah, vbh[2 * jj], vbh[2 * jj + 1]);
                    mma_bf16(c, pah, vbl[2 * jj], vbl[2 * jj + 1]);
                    mma_bf16(c, pal, vbh[2 * jj], vbh[2 * jj + 1]);
                }
            }
        }
        __syncthreads();
    }

    // epilogue: normalize, write ctx hi/lo
    const float inv0 = 1.f / lrow[0], inv1 = 1.f / lrow[1];
    const int t0 = m0 + warp * 16 + g, t1 = t0 + 8;
    #pragma unroll
    for (int j = 0; j < 8; ++j) {
        int col = h * DD + j * 8 + 2 * tg;
        unsigned hh, ll;
        split_pk(o[j][0] * inv0, o[j][1] * inv0, hh, ll);
        *(unsigned*)(ch + (bt0 + t0) * CC + col) = hh;
        *(unsigned*)(cl + (bt0 + t0) * CC + col) = ll;
        split_pk(o[j][2] * inv1, o[j][3] * inv1, hh, ll);
        *(unsigned*)(ch + (bt0 + t1) * CC + col) = hh;
        *(unsigned*)(cl + (bt0 + t1) * CC + col) = ll;
    }
}

// ----------------------------------------------------------------------------
extern "C" void kernel_launch(void* const* d_in, const int* in_sizes, int n_in,
                              void* d_out, int out_size)
{
    const float* x     = (const float*)d_in[0];
    const float* w_qkv = (const float*)d_in[1];
    const float* w_out = (const float*)d_in[2];
    const float* b_out = (const float*)d_in[3];
    float* out = (float*)d_out;

    __nv_bfloat16 *xh, *xl, *wqh, *wql, *woh, *wol, *qkvh, *qkvl, *ctxh, *ctxl;
    cudaGetSymbolAddress((void**)&xh, g_xh);
    cudaGetSymbolAddress((void**)&xl, g_xl);
    cudaGetSymbolAddress((void**)&wqh, g_wqh);
    cudaGetSymbolAddress((void**)&wql, g_wql);
    cudaGetSymbolAddress((void**)&woh, g_woh);
    cudaGetSymbolAddress((void**)&wol, g_wol);
    cudaGetSymbolAddress((void**)&qkvh, g_qkvh);
    cudaGetSymbolAddress((void**)&qkvl, g_qkvl);
    cudaGetSymbolAddress((void**)&ctxh, g_ctxh);
    cudaGetSymbolAddress((void**)&ctxl, g_ctxl);

    static bool attr_set = false;
    if (!attr_set) {
        cudaFuncSetAttribute(gemm_sp<true, false>,
                             cudaFuncAttributeMaxDynamicSharedMemorySize, GEMM_SMEM);
        cudaFuncSetAttribute(gemm_sp<false, true>,
                             cudaFuncAttributeMaxDynamicSharedMemorySize, GEMM_SMEM);
        cudaFuncSetAttribute(attn_tc,
                             cudaFuncAttributeMaxDynamicSharedMemorySize, ATTN_SMEM);
        attr_set = true;
    }

    const int M = BB * TT;
    const float QSCALE = 0.125f * 1.44269504f;  // D^-0.5 * log2(e)

    // 0) split inputs into bf16 hi/lo planes
    {
        int n2;
        n2 = M * CC / 2;
        split_kernel<<<(n2 + 255) / 256, 256>>>((const float2*)x, (unsigned*)xh, (unsigned*)xl, n2);
        n2 = CC * 3 * CC / 2;
        split_kernel<<<(n2 + 255) / 256, 256>>>((const float2*)w_qkv, (unsigned*)wqh, (unsigned*)wql, n2);
        n2 = CC * CC / 2;
        split_kernel<<<(n2 + 255) / 256, 256>>>((const float2*)w_out, (unsigned*)woh, (unsigned*)wol, n2);
    }

    // 1) qkv = x @ w_qkv -> hi/lo planes, q columns pre-scaled into log2 domain
    gemm_sp<true, false><<<dim3(3 * CC / 128, M / 128), 256, GEMM_SMEM>>>(
        xh, xl, wqh, wql, nullptr, qkvh, qkvl, nullptr, M, 3 * CC, CC, QSCALE, CC);

    // 2) causal flash attention (tensor cores) -> ctx hi/lo
    attn_tc<<<dim3(TT / 128, BB * HH), 256, ATTN_SMEM>>>(qkvh, qkvl, ctxh, ctxl);

    // 3) out = ctx @ w_out + b_out
    gemm_sp<false, true><<<dim3(CC / 128, M / 128), 256, GEMM_SMEM>>>(
        ctxh, ctxl, woh, wol, out, nullptr, nullptr, b_out, M, CC, CC, 1.f, 0);
}

// round 5
// speedup vs baseline: 3.4357x; 1.0764x over previous
#include <cuda_runtime.h>
#include <cuda_bf16.h>
#include <cuda_fp16.h>
#include <math.h>

#define BB 4
#define TT 2048
#define CC 1024
#define HH 16
#define DD 64
// M = BB*TT = 8192

// ---------------- scratch (device globals; no allocations) ------------------
__device__ __nv_bfloat16 g_xh[(size_t)BB * TT * CC];
__device__ __nv_bfloat16 g_xl[(size_t)BB * TT * CC];
__device__ __nv_bfloat16 g_wqh[(size_t)CC * 3 * CC];
__device__ __nv_bfloat16 g_wql[(size_t)CC * 3 * CC];
__device__ __nv_bfloat16 g_woh[(size_t)CC * CC];
__device__ __nv_bfloat16 g_wol[(size_t)CC * CC];
__device__ __half        g_qk16[(size_t)BB * TT * 2 * CC];  // q (scaled) | k, fp16
__device__ __nv_bfloat16 g_vh[(size_t)BB * TT * CC];
__device__ __nv_bfloat16 g_vl[(size_t)BB * TT * CC];
__device__ __nv_bfloat16 g_ctxh[(size_t)BB * TT * CC];
__device__ __nv_bfloat16 g_ctxl[(size_t)BB * TT * CC];

// ---------------- helpers ----------------------------------------------------
__device__ __forceinline__ unsigned pk2(float lo, float hi) {
    unsigned r;
    asm("cvt.rn.bf16x2.f32 %0, %1, %2;" : "=r"(r) : "f"(hi), "f"(lo));
    return r;
}
__device__ __forceinline__ void split_pk(float x0, float x1, unsigned& h, unsigned& l) {
    h = pk2(x0, x1);
    float h0 = __int_as_float(h << 16);
    float h1 = __int_as_float(h & 0xFFFF0000u);
    l = pk2(x0 - h0, x1 - h1);
}
__device__ __forceinline__ void mma_bf16(float* c, const unsigned* a,
                                         unsigned b0, unsigned b1) {
    asm volatile(
        "mma.sync.aligned.m16n8k16.row.col.f32.bf16.bf16.f32 "
        "{%0,%1,%2,%3}, {%4,%5,%6,%7}, {%8,%9}, {%0,%1,%2,%3};"
        : "+f"(c[0]), "+f"(c[1]), "+f"(c[2]), "+f"(c[3])
        : "r"(a[0]), "r"(a[1]), "r"(a[2]), "r"(a[3]), "r"(b0), "r"(b1));
}
__device__ __forceinline__ void mma_f16(float* c, const unsigned* a,
                                        unsigned b0, unsigned b1) {
    asm volatile(
        "mma.sync.aligned.m16n8k16.row.col.f32.f16.f16.f32 "
        "{%0,%1,%2,%3}, {%4,%5,%6,%7}, {%8,%9}, {%0,%1,%2,%3};"
        : "+f"(c[0]), "+f"(c[1]), "+f"(c[2]), "+f"(c[3])
        : "r"(a[0]), "r"(a[1]), "r"(a[2]), "r"(a[3]), "r"(b0), "r"(b1));
}
__device__ __forceinline__ void ldsm4(unsigned* r, const void* p) {
    unsigned a = (unsigned)__cvta_generic_to_shared(p);
    asm volatile("ldmatrix.sync.aligned.m8n8.x4.shared.b16 {%0,%1,%2,%3}, [%4];"
                 : "=r"(r[0]), "=r"(r[1]), "=r"(r[2]), "=r"(r[3]) : "r"(a));
}
__device__ __forceinline__ void ldsm4t(unsigned* r, const void* p) {
    unsigned a = (unsigned)__cvta_generic_to_shared(p);
    asm volatile("ldmatrix.sync.aligned.m8n8.x4.trans.shared.b16 {%0,%1,%2,%3}, [%4];"
                 : "=r"(r[0]), "=r"(r[1]), "=r"(r[2]), "=r"(r[3]) : "r"(a));
}
__device__ __forceinline__ void cp16(const void* sdst, const void* gsrc) {
    unsigned d = (unsigned)__cvta_generic_to_shared(sdst);
    asm volatile("cp.async.ca.shared.global [%0], [%1], 16;" :: "r"(d), "l"(gsrc));
}
__device__ __forceinline__ void cp_commit() { asm volatile("cp.async.commit_group;"); }

// exp2 via magic-round + poly (FMA pipe only, no MUFU)
__device__ __forceinline__ float exp2p(float p) {
    p = fmaxf(p, -120.f);
    float t = p + 12582912.f;
    int ii = __float_as_int(t) - 0x4B400000;
    float f = p - (t - 12582912.f);
    float r = 1.5403530e-4f;
    r = fmaf(r, f, 1.3333558e-3f);
    r = fmaf(r, f, 9.6181291e-3f);
    r = fmaf(r, f, 5.5504109e-2f);
    r = fmaf(r, f, 2.4022651e-1f);
    r = fmaf(r, f, 6.9314718e-1f);
    r = fmaf(r, f, 1.0f);
    return r * __int_as_float((ii + 127) << 23);
}

// ---------------- input split kernel -----------------------------------------
__global__ void split_kernel(const float2* __restrict__ src,
                             unsigned* __restrict__ hi, unsigned* __restrict__ lo, int n2)
{
    int i = blockIdx.x * blockDim.x + threadIdx.x;
    if (i < n2) {
        float2 v = src[i];
        unsigned h, l;
        split_pk(v.x, v.y, h, l);
        hi[i] = h; lo[i] = l;
    }
}

// ---------------- GEMM on split bf16 inputs (bf16x3) ---------------------------
// C = A @ B. BM=BN=128, BK=32, 256 thr, double-buffered cp.async.
// SPLIT_OUT (QKV): cols [0,2C) -> fp16 single plane (q scaled); cols [2C,3C) -> v bf16 hi/lo.
#define GEMM_SMEM 75776
template <bool SPLIT_OUT, bool BIAS>
__global__ __launch_bounds__(256, 2)
void gemm_sp(const __nv_bfloat16* __restrict__ Ah, const __nv_bfloat16* __restrict__ Al,
             const __nv_bfloat16* __restrict__ Bh, const __nv_bfloat16* __restrict__ Bl,
             float* __restrict__ Cf, __half* __restrict__ Qk,
             __nv_bfloat16* __restrict__ Vh, __nv_bfloat16* __restrict__ Vl,
             const float* __restrict__ bias,
             int M, int N, int K, float qscale, int qcols)
{
    extern __shared__ __nv_bfloat16 sm[];
    const int tid = threadIdx.x, warp = tid >> 5, lane = tid & 31;
    const int wm = warp & 3, wn = warp >> 2;
    const int bm = blockIdx.y * 128, bn = blockIdx.x * 128;

    auto As = [&](int buf, int t) { return sm + buf * 18944 + t * 5120; };
    auto Bs = [&](int buf, int t) { return sm + buf * 18944 + 10240 + t * 4352; };

    float acc[2][8][4];
    #pragma unroll
    for (int i = 0; i < 2; ++i)
        #pragma unroll
        for (int j = 0; j < 8; ++j)
            #pragma unroll
            for (int q = 0; q < 4; ++q) acc[i][j][q] = 0.f;

    auto loadbuf = [&](int buf, int k0) {
        #pragma unroll
        for (int t = 0; t < 2; ++t) {
            const __nv_bfloat16* Ag = t ? Al : Ah;
            #pragma unroll
            for (int c = 0; c < 2; ++c) {
                int id = tid + c * 256;
                int row = id >> 2, col8 = (id & 3) << 3;
                cp16(As(buf, t) + row * 40 + col8,
                     Ag + (size_t)(bm + row) * K + k0 + col8);
            }
            const __nv_bfloat16* Bg = t ? Bl : Bh;
            #pragma unroll
            for (int c = 0; c < 2; ++c) {
                int id = tid + c * 256;
                int row = id >> 4, col8 = (id & 15) << 3;
                cp16(Bs(buf, t) + row * 136 + col8,
                     Bg + (size_t)(k0 + row) * N + bn + col8);
            }
        }
    };

    const int iters = K >> 5;
    loadbuf(0, 0);
    cp_commit();

    for (int it = 0; it < iters; ++it) {
        if (it + 1 < iters) {
            loadbuf((it + 1) & 1, (it + 1) << 5);
            cp_commit();
            asm volatile("cp.async.wait_group 1;" ::: "memory");
        } else {
            asm volatile("cp.async.wait_group 0;" ::: "memory");
        }
        __syncthreads();
        const int buf = it & 1;

        #pragma unroll
        for (int kk = 0; kk < 2; ++kk) {
            unsigned af[2][2][4];
            #pragma unroll
            for (int i = 0; i < 2; ++i)
                #pragma unroll
                for (int t = 0; t < 2; ++t)
                    ldsm4(af[i][t], As(buf, t) +
                          (wm * 32 + i * 16 + (lane & 15)) * 40 + kk * 16 + ((lane >> 4) << 3));
            #pragma unroll
            for (int p = 0; p < 4; ++p) {
                unsigned bh_[4], bl_[4];
                const __nv_bfloat16* bp0 = Bs(buf, 0) +
                    (kk * 16 + (lane & 15)) * 136 + wn * 64 + p * 16 + ((lane >> 4) << 3);
                const __nv_bfloat16* bp1 = Bs(buf, 1) +
                    (kk * 16 + (lane & 15)) * 136 + wn * 64 + p * 16 + ((lane >> 4) << 3);
                ldsm4t(bh_, bp0);
                ldsm4t(bl_, bp1);
                #pragma unroll
                for (int i = 0; i < 2; ++i)
                    #pragma unroll
                    for (int jj = 0; jj < 2; ++jj) {
                        float* c = acc[i][2 * p + jj];
                        mma_bf16(c, af[i][0], bh_[2 * jj], bh_[2 * jj + 1]);
                        mma_bf16(c, af[i][0], bl_[2 * jj], bl_[2 * jj + 1]);
                        mma_bf16(c, af[i][1], bh_[2 * jj], bh_[2 * jj + 1]);
                    }
            }
        }
        __syncthreads();
    }

    // epilogue
    const int g = lane >> 2, tg = lane & 3;
    #pragma unroll
    for (int i = 0; i < 2; ++i) {
        int row0 = bm + wm * 32 + i * 16 + g;
        #pragma unroll
        for (int j = 0; j < 8; ++j) {
            int col = bn + wn * 64 + j * 8 + 2 * tg;
            float v0 = acc[i][j][0], v1 = acc[i][j][1];
            float v2 = acc[i][j][2], v3 = acc[i][j][3];
            if (SPLIT_OUT) {
                if (col < 2 * CC) {  // q or k -> fp16 single plane
                    float fac = (col < qcols) ? qscale : 1.f;
                    *(__half2*)(Qk + (size_t)row0 * (2 * CC) + col) =
                        __floats2half2_rn(v0 * fac, v1 * fac);
                    *(__half2*)(Qk + (size_t)(row0 + 8) * (2 * CC) + col) =
                        __floats2half2_rn(v2 * fac, v3 * fac);
                } else {             // v -> bf16 hi/lo
                    int vc = col - 2 * CC;
                    unsigned h, l;
                    split_pk(v0, v1, h, l);
                    *(unsigned*)(Vh + (size_t)row0 * CC + vc) = h;
                    *(unsigned*)(Vl + (size_t)row0 * CC + vc) = l;
                    split_pk(v2, v3, h, l);
                    *(unsigned*)(Vh + (size_t)(row0 + 8) * CC + vc) = h;
                    *(unsigned*)(Vl + (size_t)(row0 + 8) * CC + vc) = l;
                }
            } else {
                float b0 = 0.f, b1 = 0.f;
                if (BIAS) { b0 = bias[col]; b1 = bias[col + 1]; }
                float2 w0 = make_float2(v0 + b0, v1 + b1);
                float2 w1 = make_float2(v2 + b0, v3 + b1);
                *(float2*)&Cf[(size_t)row0 * N + col] = w0;
                *(float2*)&Cf[(size_t)(row0 + 8) * N + col] = w1;
            }
        }
    }
}

// ---------------- tensor-core causal flash attention ---------------------------
// BM=128 (8 warps x 16 rows), BN=64. S = fp16 single-plane MMA (q pre-scaled,
// log2 domain). PV = bf16x3. Smem 73728 B -> 2 CTAs/SM.
#define ATTN_SMEM 73728
__global__ __launch_bounds__(256, 2)
void attn_tc(const __half* __restrict__ qk,
             const __nv_bfloat16* __restrict__ vh, const __nv_bfloat16* __restrict__ vl,
             __nv_bfloat16* __restrict__ ch, __nv_bfloat16* __restrict__ cl)
{
    extern __shared__ char smc[];
    // Q fp16 128x72 @0 (18432 B). KV buf b @18432 + b*27648:
    //   K fp16 64x72 (+0, 9216 B), Vh bf16 64x72 (+9216), Vl bf16 64x72 (+18432)
    const int tid = threadIdx.x, warp = tid >> 5, lane = tid & 31;
    const int g = lane >> 2, tg = lane & 3;
    const int bh = blockIdx.y;
    const int b = bh / HH, h = bh % HH;
    const int m0 = blockIdx.x * 128;
    const size_t bt0 = (size_t)b * TT;
    const int colq = h * DD, colk = CC + h * DD, colv = h * DD;

    __half* Qs = (__half*)smc;

    auto load_kv = [&](int it, int buf) {
        const int n0 = it * 64;
        char* base = smc + 18432 + buf * 27648;
        #pragma unroll
        for (int c = 0; c < 2; ++c) {
            int id = tid + c * 256;               // 0..511
            int row = id >> 3, col8 = (id & 7) << 3;
            cp16((__half*)base + row * 72 + col8,
                 qk + (bt0 + n0 + row) * (2 * CC) + colk + col8);
            cp16((__nv_bfloat16*)(base + 9216) + row * 72 + col8,
                 vh + (bt0 + n0 + row) * CC + colv + col8);
            cp16((__nv_bfloat16*)(base + 18432) + row * 72 + col8,
                 vl + (bt0 + n0 + row) * CC + colv + col8);
        }
    };

    // Q load (fp16 single plane)
    #pragma unroll
    for (int c = 0; c < 4; ++c) {
        int id = tid + c * 256;                   // 0..1023
        int row = id >> 3, col8 = (id & 7) << 3;
        cp16(Qs + row * 72 + col8, qk + (bt0 + m0 + row) * (2 * CC) + colq + col8);
    }
    load_kv(0, 0);
    cp_commit();

    unsigned qf[4][4];
    float o[8][4];
    float mrow[2] = {-1e30f, -1e30f}, lrow[2] = {0.f, 0.f};
    #pragma unroll
    for (int j = 0; j < 8; ++j)
        #pragma unroll
        for (int q = 0; q < 4; ++q) o[j][q] = 0.f;

    const int nt = (m0 >> 6) + 2;
    for (int it = 0; it < nt; ++it) {
        if (it + 1 < nt) {
            load_kv(it + 1, (it + 1) & 1);
            cp_commit();
            asm volatile("cp.async.wait_group 1;" ::: "memory");
        } else {
            asm volatile("cp.async.wait_group 0;" ::: "memory");
        }
        __syncthreads();

        if (it == 0) {
            #pragma unroll
            for (int kk = 0; kk < 4; ++kk)
                ldsm4(qf[kk], Qs + (warp * 16 + (lane & 15)) * 72 +
                              kk * 16 + ((lane >> 4) << 3));
        }

        char* base = smc + 18432 + (it & 1) * 27648;
        const __half* Ks = (const __half*)base;
        const __nv_bfloat16* Vh_ = (const __nv_bfloat16*)(base + 9216);
        const __nv_bfloat16* Vl_ = (const __nv_bfloat16*)(base + 18432);
        const int n0 = it * 64;

        // S = Q K^T (fp16 single plane, log2 domain)
        float sc[8][4];
        #pragma unroll
        for (int j = 0; j < 8; ++j)
            #pragma unroll
            for (int q = 0; q < 4; ++q) sc[j][q] = 0.f;

        #pragma unroll
        for (int kk = 0; kk < 4; ++kk) {
            #pragma unroll
            for (int p = 0; p < 4; ++p) {
                const int krow = p * 16 + (lane & 7) + ((lane >> 4) << 3);
                const int kcol = kk * 16 + (((lane >> 3) & 1) << 3);
                unsigned kb[4];
                ldsm4(kb, Ks + krow * 72 + kcol);
                #pragma unroll
                for (int jj = 0; jj < 2; ++jj)
                    mma_f16(sc[2 * p + jj], qf[kk], kb[2 * jj], kb[2 * jj + 1]);
            }
        }

        // causal mask
        const int r0 = m0 + warp * 16 + g, r1 = r0 + 8;
        if (n0 + 63 > m0) {
            #pragma unroll
            for (int j = 0; j < 8; ++j) {
                int cb = n0 + j * 8 + 2 * tg;
                if (cb > r0) sc[j][0] = -1e30f;
                if (cb + 1 > r0) sc[j][1] = -1e30f;
                if (cb > r1) sc[j][2] = -1e30f;
                if (cb + 1 > r1) sc[j][3] = -1e30f;
            }
        }

        // online softmax, base-2
        #pragma unroll
        for (int r = 0; r < 2; ++r) {
            float mx = -1e30f;
            #pragma unroll
            for (int j = 0; j < 8; ++j)
                mx = fmaxf(mx, fmaxf(sc[j][2 * r], sc[j][2 * r + 1]));
            mx = fmaxf(mx, __shfl_xor_sync(0xffffffffu, mx, 1));
            mx = fmaxf(mx, __shfl_xor_sync(0xffffffffu, mx, 2));
            float mnew = fmaxf(mrow[r], mx);
            float alpha = exp2p(mrow[r] - mnew);
            mrow[r] = mnew;
            float rsum = 0.f;
            #pragma unroll
            for (int j = 0; j < 8; ++j) {
                float p0 = exp2p(sc[j][2 * r] - mnew);
                float p1 = exp2p(sc[j][2 * r + 1] - mnew);
                sc[j][2 * r] = p0; sc[j][2 * r + 1] = p1;
                rsum += p0 + p1;
            }
            rsum += __shfl_xor_sync(0xffffffffu, rsum, 1);
            rsum += __shfl_xor_sync(0xffffffffu, rsum, 2);
            lrow[r] = lrow[r] * alpha + rsum;
            #pragma unroll
            for (int j = 0; j < 8; ++j) {
                o[j][2 * r] *= alpha;
                o[j][2 * r + 1] *= alpha;
            }
        }

        // O += P V (P split bf16 hi/lo, V bf16 hi/lo: 3-term)
        #pragma unroll
        for (int s = 0; s < 4; ++s) {
            unsigned pah[4], pal[4];
            split_pk(sc[2 * s][0], sc[2 * s][1], pah[0], pal[0]);
            split_pk(sc[2 * s][2], sc[2 * s][3], pah[1], pal[1]);
            split_pk(sc[2 * s + 1][0], sc[2 * s + 1][1], pah[2], pal[2]);
            split_pk(sc[2 * s + 1][2], sc[2 * s + 1][3], pah[3], pal[3]);
            #pragma unroll
            for (int p = 0; p < 4; ++p) {
                const int vrow = s * 16 + (lane & 15);
                const int vcol = p * 16 + ((lane >> 4) << 3);
                unsigned vbh[4], vbl[4];
                ldsm4t(vbh, Vh_ + vrow * 72 + vcol);
                ldsm4t(vbl, Vl_ + vrow * 72 + vcol);
                #pragma unroll
                for (int jj = 0; jj < 2; ++jj) {
                    float* c = o[2 * p + jj];
                    mma_bf16(c, pah, vbh[2 * jj], vbh[2 * jj + 1]);
                    mma_bf16(c, pah, vbl[2 * jj], vbl[2 * jj + 1]);
                    mma_bf16(c, pal, vbh[2 * jj], vbh[2 * jj + 1]);
                }
            }
        }
        __syncthreads();
    }

    // epilogue: normalize, write ctx hi/lo
    const float inv0 = 1.f / lrow[0], inv1 = 1.f / lrow[1];
    const int t0 = m0 + warp * 16 + g, t1 = t0 + 8;
    #pragma unroll
    for (int j = 0; j < 8; ++j) {
        int col = h * DD + j * 8 + 2 * tg;
        unsigned hh, ll;
        split_pk(o[j][0] * inv0, o[j][1] * inv0, hh, ll);
        *(unsigned*)(ch + (bt0 + t0) * CC + col) = hh;
        *(unsigned*)(cl + (bt0 + t0) * CC + col) = ll;
        split_pk(o[j][2] * inv1, o[j][3] * inv1, hh, ll);
        *(unsigned*)(ch + (bt0 + t1) * CC + col) = hh;
        *(unsigned*)(cl + (bt0 + t1) * CC + col) = ll;
    }
}

// ----------------------------------------------------------------------------
extern "C" void kernel_launch(void* const* d_in, const int* in_sizes, int n_in,
                              void* d_out, int out_size)
{
    const float* x     = (const float*)d_in[0];
    const float* w_qkv = (const float*)d_in[1];
    const float* w_out = (const float*)d_in[2];
    const float* b_out = (const float*)d_in[3];
    float* out = (float*)d_out;

    __nv_bfloat16 *xh, *xl, *wqh, *wql, *woh, *wol, *vh, *vl, *ctxh, *ctxl;
    __half* qk16;
    cudaGetSymbolAddress((void**)&xh, g_xh);
    cudaGetSymbolAddress((void**)&xl, g_xl);
    cudaGetSymbolAddress((void**)&wqh, g_wqh);
    cudaGetSymbolAddress((void**)&wql, g_wql);
    cudaGetSymbolAddress((void**)&woh, g_woh);
    cudaGetSymbolAddress((void**)&wol, g_wol);
    cudaGetSymbolAddress((void**)&qk16, g_qk16);
    cudaGetSymbolAddress((void**)&vh, g_vh);
    cudaGetSymbolAddress((void**)&vl, g_vl);
    cudaGetSymbolAddress((void**)&ctxh, g_ctxh);
    cudaGetSymbolAddress((void**)&ctxl, g_ctxl);

    static bool attr_set = false;
    if (!attr_set) {
        cudaFuncSetAttribute(gemm_sp<true, false>,
                             cudaFuncAttributeMaxDynamicSharedMemorySize, GEMM_SMEM);
        cudaFuncSetAttribute(gemm_sp<false, true>,
                             cudaFuncAttributeMaxDynamicSharedMemorySize, GEMM_SMEM);
        cudaFuncSetAttribute(attn_tc,
                             cudaFuncAttributeMaxDynamicSharedMemorySize, ATTN_SMEM);
        attr_set = true;
    }

    const int M = BB * TT;
    const float QSCALE = 0.125f * 1.44269504f;  // D^-0.5 * log2(e)

    // 0) split inputs into bf16 hi/lo planes
    {
        int n2;
        n2 = M * CC / 2;
        split_kernel<<<(n2 + 255) / 256, 256>>>((const float2*)x, (unsigned*)xh, (unsigned*)xl, n2);
        n2 = CC * 3 * CC / 2;
        split_kernel<<<(n2 + 255) / 256, 256>>>((const float2*)w_qkv, (unsigned*)wqh, (unsigned*)wql, n2);
        n2 = CC * CC / 2;
        split_kernel<<<(n2 + 255) / 256, 256>>>((const float2*)w_out, (unsigned*)woh, (unsigned*)wol, n2);
    }

    // 1) qkv = x @ w_qkv -> q,k fp16 (q in log2 domain), v bf16 hi/lo
    gemm_sp<true, false><<<dim3(3 * CC / 128, M / 128), 256, GEMM_SMEM>>>(
        xh, xl, wqh, wql, nullptr, qk16, vh, vl, nullptr, M, 3 * CC, CC, QSCALE, CC);

    // 2) causal flash attention (fp16 S, bf16x3 PV) -> ctx hi/lo
    attn_tc<<<dim3(TT / 128, BB * HH), 256, ATTN_SMEM>>>(qk16, vh, vl, ctxh, ctxl);

    // 3) out = ctx @ w_out + b_out
    gemm_sp<false, true><<<dim3(CC / 128, M / 128), 256, GEMM_SMEM>>>(
        ctxh, ctxl, woh, wol, out, nullptr, nullptr, nullptr, b_out, M, CC, CC, 1.f, 0);
}

// round 6
// speedup vs baseline: 3.5136x; 1.0227x over previous
#include <cuda_runtime.h>
#include <cuda_bf16.h>
#include <cuda_fp16.h>
#include <math.h>

#define BB 4
#define TT 2048
#define CC 1024
#define HH 16
#define DD 64
// M = BB*TT = 8192

// ---------------- scratch (device globals; no allocations) ------------------
__device__ __nv_bfloat16 g_xh[(size_t)BB * TT * CC];
__device__ __nv_bfloat16 g_xl[(size_t)BB * TT * CC];
__device__ __nv_bfloat16 g_wqh[(size_t)CC * 3 * CC];
__device__ __nv_bfloat16 g_wql[(size_t)CC * 3 * CC];
__device__ __nv_bfloat16 g_woh[(size_t)CC * CC];
__device__ __nv_bfloat16 g_wol[(size_t)CC * CC];
__device__ __half        g_qk16[(size_t)BB * TT * 2 * CC];  // q (scaled) | k, fp16
__device__ __nv_bfloat16 g_vh[(size_t)BB * TT * CC];
__device__ __nv_bfloat16 g_vl[(size_t)BB * TT * CC];
__device__ __nv_bfloat16 g_ctxh[(size_t)BB * TT * CC];
__device__ __nv_bfloat16 g_ctxl[(size_t)BB * TT * CC];

// ---------------- helpers ----------------------------------------------------
__device__ __forceinline__ unsigned pk2(float lo, float hi) {
    unsigned r;
    asm("cvt.rn.bf16x2.f32 %0, %1, %2;" : "=r"(r) : "f"(hi), "f"(lo));
    return r;
}
__device__ __forceinline__ void split_pk(float x0, float x1, unsigned& h, unsigned& l) {
    h = pk2(x0, x1);
    float h0 = __int_as_float(h << 16);
    float h1 = __int_as_float(h & 0xFFFF0000u);
    l = pk2(x0 - h0, x1 - h1);
}
__device__ __forceinline__ void mma_bf16(float* c, const unsigned* a,
                                         unsigned b0, unsigned b1) {
    asm volatile(
        "mma.sync.aligned.m16n8k16.row.col.f32.bf16.bf16.f32 "
        "{%0,%1,%2,%3}, {%4,%5,%6,%7}, {%8,%9}, {%0,%1,%2,%3};"
        : "+f"(c[0]), "+f"(c[1]), "+f"(c[2]), "+f"(c[3])
        : "r"(a[0]), "r"(a[1]), "r"(a[2]), "r"(a[3]), "r"(b0), "r"(b1));
}
__device__ __forceinline__ void mma_f16(float* c, const unsigned* a,
                                        unsigned b0, unsigned b1) {
    asm volatile(
        "mma.sync.aligned.m16n8k16.row.col.f32.f16.f16.f32 "
        "{%0,%1,%2,%3}, {%4,%5,%6,%7}, {%8,%9}, {%0,%1,%2,%3};"
        : "+f"(c[0]), "+f"(c[1]), "+f"(c[2]), "+f"(c[3])
        : "r"(a[0]), "r"(a[1]), "r"(a[2]), "r"(a[3]), "r"(b0), "r"(b1));
}
__device__ __forceinline__ void ldsm4(unsigned* r, const void* p) {
    unsigned a = (unsigned)__cvta_generic_to_shared(p);
    asm volatile("ldmatrix.sync.aligned.m8n8.x4.shared.b16 {%0,%1,%2,%3}, [%4];"
                 : "=r"(r[0]), "=r"(r[1]), "=r"(r[2]), "=r"(r[3]) : "r"(a));
}
__device__ __forceinline__ void ldsm4t(unsigned* r, const void* p) {
    unsigned a = (unsigned)__cvta_generic_to_shared(p);
    asm volatile("ldmatrix.sync.aligned.m8n8.x4.trans.shared.b16 {%0,%1,%2,%3}, [%4];"
                 : "=r"(r[0]), "=r"(r[1]), "=r"(r[2]), "=r"(r[3]) : "r"(a));
}
__device__ __forceinline__ void cp16(const void* sdst, const void* gsrc) {
    unsigned d = (unsigned)__cvta_generic_to_shared(sdst);
    asm volatile("cp.async.ca.shared.global [%0], [%1], 16;" :: "r"(d), "l"(gsrc));
}
__device__ __forceinline__ void cp_commit() { asm volatile("cp.async.commit_group;"); }

// exp2 via magic-round + poly (FMA pipe only, no MUFU)
__device__ __forceinline__ float exp2p(float p) {
    p = fmaxf(p, -120.f);
    float t = p + 12582912.f;
    int ii = __float_as_int(t) - 0x4B400000;
    float f = p - (t - 12582912.f);
    float r = 1.5403530e-4f;
    r = fmaf(r, f, 1.3333558e-3f);
    r = fmaf(r, f, 9.6181291e-3f);
    r = fmaf(r, f, 5.5504109e-2f);
    r = fmaf(r, f, 2.4022651e-1f);
    r = fmaf(r, f, 6.9314718e-1f);
    r = fmaf(r, f, 1.0f);
    return r * __int_as_float((ii + 127) << 23);
}

// ---------------- input split kernel -----------------------------------------
__global__ void split_kernel(const float2* __restrict__ src,
                             unsigned* __restrict__ hi, unsigned* __restrict__ lo, int n2)
{
    int i = blockIdx.x * blockDim.x + threadIdx.x;
    if (i < n2) {
        float2 v = src[i];
        unsigned h, l;
        split_pk(v.x, v.y, h, l);
        hi[i] = h; lo[i] = l;
    }
}

// ---------------- GEMM on split bf16 inputs (bf16x3) ---------------------------
// C = A @ B. BM=BN=128, BK=32, 256 thr, 3-stage cp.async pipeline (1 sync/chunk).
// SPLIT_OUT (QKV): cols [0,2C) -> fp16 single plane (q scaled); cols [2C,3C) -> v bf16 hi/lo.
#define GEMM_SMEM 113664
template <bool SPLIT_OUT, bool BIAS>
__global__ __launch_bounds__(256, 2)
void gemm_sp(const __nv_bfloat16* __restrict__ Ah, const __nv_bfloat16* __restrict__ Al,
             const __nv_bfloat16* __restrict__ Bh, const __nv_bfloat16* __restrict__ Bl,
             float* __restrict__ Cf, __half* __restrict__ Qk,
             __nv_bfloat16* __restrict__ Vh, __nv_bfloat16* __restrict__ Vl,
             const float* __restrict__ bias,
             int M, int N, int K, float qscale, int qcols)
{
    extern __shared__ __nv_bfloat16 sm[];
    const int tid = threadIdx.x, warp = tid >> 5, lane = tid & 31;
    const int wm = warp & 3, wn = warp >> 2;
    const int bm = blockIdx.y * 128, bn = blockIdx.x * 128;

    auto As = [&](int buf, int t) { return sm + buf * 18944 + t * 5120; };
    auto Bs = [&](int buf, int t) { return sm + buf * 18944 + 10240 + t * 4352; };

    float acc[2][8][4];
    #pragma unroll
    for (int i = 0; i < 2; ++i)
        #pragma unroll
        for (int j = 0; j < 8; ++j)
            #pragma unroll
            for (int q = 0; q < 4; ++q) acc[i][j][q] = 0.f;

    auto loadbuf = [&](int buf, int k0) {
        #pragma unroll
        for (int t = 0; t < 2; ++t) {
            const __nv_bfloat16* Ag = t ? Al : Ah;
            #pragma unroll
            for (int c = 0; c < 2; ++c) {
                int id = tid + c * 256;
                int row = id >> 2, col8 = (id & 3) << 3;
                cp16(As(buf, t) + row * 40 + col8,
                     Ag + (size_t)(bm + row) * K + k0 + col8);
            }
            const __nv_bfloat16* Bg = t ? Bl : Bh;
            #pragma unroll
            for (int c = 0; c < 2; ++c) {
                int id = tid + c * 256;
                int row = id >> 4, col8 = (id & 15) << 3;
                cp16(Bs(buf, t) + row * 136 + col8,
                     Bg + (size_t)(k0 + row) * N + bn + col8);
            }
        }
    };

    const int iters = K >> 5;
    loadbuf(0, 0);  cp_commit();
    loadbuf(1, 32); cp_commit();

    int cur = 0, ldb = 2;  // compute buffer, load-target buffer
    for (int it = 0; it < iters; ++it) {
        if (it + 1 < iters) asm volatile("cp.async.wait_group 1;" ::: "memory");
        else                asm volatile("cp.async.wait_group 0;" ::: "memory");
        __syncthreads();

        #pragma unroll
        for (int kk = 0; kk < 2; ++kk) {
            unsigned af[2][2][4];
            #pragma unroll
            for (int i = 0; i < 2; ++i)
                #pragma unroll
                for (int t = 0; t < 2; ++t)
                    ldsm4(af[i][t], As(cur, t) +
                          (wm * 32 + i * 16 + (lane & 15)) * 40 + kk * 16 + ((lane >> 4) << 3));
            #pragma unroll
            for (int p = 0; p < 4; ++p) {
                unsigned bh_[4], bl_[4];
                const __nv_bfloat16* bp0 = Bs(cur, 0) +
                    (kk * 16 + (lane & 15)) * 136 + wn * 64 + p * 16 + ((lane >> 4) << 3);
                const __nv_bfloat16* bp1 = Bs(cur, 1) +
                    (kk * 16 + (lane & 15)) * 136 + wn * 64 + p * 16 + ((lane >> 4) << 3);
                ldsm4t(bh_, bp0);
                ldsm4t(bl_, bp1);
                #pragma unroll
                for (int i = 0; i < 2; ++i)
                    #pragma unroll
                    for (int jj = 0; jj < 2; ++jj) {
                        float* c = acc[i][2 * p + jj];
                        mma_bf16(c, af[i][0], bh_[2 * jj], bh_[2 * jj + 1]);
                        mma_bf16(c, af[i][0], bl_[2 * jj], bl_[2 * jj + 1]);
                        mma_bf16(c, af[i][1], bh_[2 * jj], bh_[2 * jj + 1]);
                    }
            }
        }

        if (it + 2 < iters) {
            loadbuf(ldb, (it + 2) << 5);
            cp_commit();
        }
        cur = (cur == 2) ? 0 : cur + 1;
        ldb = (ldb == 2) ? 0 : ldb + 1;
    }

    // epilogue
    const int g = lane >> 2, tg = lane & 3;
    #pragma unroll
    for (int i = 0; i < 2; ++i) {
        int row0 = bm + wm * 32 + i * 16 + g;
        #pragma unroll
        for (int j = 0; j < 8; ++j) {
            int col = bn + wn * 64 + j * 8 + 2 * tg;
            float v0 = acc[i][j][0], v1 = acc[i][j][1];
            float v2 = acc[i][j][2], v3 = acc[i][j][3];
            if (SPLIT_OUT) {
                if (col < 2 * CC) {  // q or k -> fp16 single plane
                    float fac = (col < qcols) ? qscale : 1.f;
                    *(__half2*)(Qk + (size_t)row0 * (2 * CC) + col) =
                        __floats2half2_rn(v0 * fac, v1 * fac);
                    *(__half2*)(Qk + (size_t)(row0 + 8) * (2 * CC) + col) =
                        __floats2half2_rn(v2 * fac, v3 * fac);
                } else {             // v -> bf16 hi/lo
                    int vc = col - 2 * CC;
                    unsigned h, l;
                    split_pk(v0, v1, h, l);
                    *(unsigned*)(Vh + (size_t)row0 * CC + vc) = h;
                    *(unsigned*)(Vl + (size_t)row0 * CC + vc) = l;
                    split_pk(v2, v3, h, l);
                    *(unsigned*)(Vh + (size_t)(row0 + 8) * CC + vc) = h;
                    *(unsigned*)(Vl + (size_t)(row0 + 8) * CC + vc) = l;
                }
            } else {
                float b0 = 0.f, b1 = 0.f;
                if (BIAS) { b0 = bias[col]; b1 = bias[col + 1]; }
                float2 w0 = make_float2(v0 + b0, v1 + b1);
                float2 w1 = make_float2(v2 + b0, v3 + b1);
                *(float2*)&Cf[(size_t)row0 * N + col] = w0;
                *(float2*)&Cf[(size_t)(row0 + 8) * N + col] = w1;
            }
        }
    }
}

// ---------------- tensor-core causal flash attention ---------------------------
// BM=128 (8 warps x 16 rows), BN=64. S = fp16 single-plane MMA (q pre-scaled,
// log2 domain). PV = bf16x3. 3-stage KV pipeline, 1 sync/tile. Smem 101376 B.
#define ATTN_SMEM 101376
__global__ __launch_bounds__(256, 2)
void attn_tc(const __half* __restrict__ qk,
             const __nv_bfloat16* __restrict__ vh, const __nv_bfloat16* __restrict__ vl,
             __nv_bfloat16* __restrict__ ch, __nv_bfloat16* __restrict__ cl)
{
    extern __shared__ char smc[];
    // Q fp16 128x72 @0 (18432 B). KV buf b @18432 + b*27648 (b in 0..2):
    //   K fp16 64x72 (+0, 9216 B), Vh bf16 64x72 (+9216), Vl bf16 64x72 (+18432)
    const int tid = threadIdx.x, warp = tid >> 5, lane = tid & 31;
    const int g = lane >> 2, tg = lane & 3;
    const int bh = blockIdx.y;
    const int b = bh / HH, h = bh % HH;
    const int m0 = blockIdx.x * 128;
    const size_t bt0 = (size_t)b * TT;
    const int colq = h * DD, colk = CC + h * DD, colv = h * DD;

    __half* Qs = (__half*)smc;

    auto load_kv = [&](int it, int buf) {
        const int n0 = it * 64;
        char* base = smc + 18432 + buf * 27648;
        #pragma unroll
        for (int c = 0; c < 2; ++c) {
            int id = tid + c * 256;               // 0..511
            int row = id >> 3, col8 = (id & 7) << 3;
            cp16((__half*)base + row * 72 + col8,
                 qk + (bt0 + n0 + row) * (2 * CC) + colk + col8);
            cp16((__nv_bfloat16*)(base + 9216) + row * 72 + col8,
                 vh + (bt0 + n0 + row) * CC + colv + col8);
            cp16((__nv_bfloat16*)(base + 18432) + row * 72 + col8,
                 vl + (bt0 + n0 + row) * CC + colv + col8);
        }
    };

    // Q load (fp16 single plane), grouped with KV tile 0
    #pragma unroll
    for (int c = 0; c < 4; ++c) {
        int id = tid + c * 256;                   // 0..1023
        int row = id >> 3, col8 = (id & 7) << 3;
        cp16(Qs + row * 72 + col8, qk + (bt0 + m0 + row) * (2 * CC) + colq + col8);
    }
    const int nt = (m0 >> 6) + 2;
    load_kv(0, 0);
    cp_commit();
    if (nt > 1) { load_kv(1, 1); cp_commit(); }

    unsigned qf[4][4];
    float o[8][4];
    float mrow[2] = {-1e30f, -1e30f}, lrow[2] = {0.f, 0.f};
    #pragma unroll
    for (int j = 0; j < 8; ++j)
        #pragma unroll
        for (int q = 0; q < 4; ++q) o[j][q] = 0.f;

    int cur = 0, ldb = 2;
    for (int it = 0; it < nt; ++it) {
        if (it + 1 < nt) asm volatile("cp.async.wait_group 1;" ::: "memory");
        else             asm volatile("cp.async.wait_group 0;" ::: "memory");
        __syncthreads();

        if (it == 0) {
            #pragma unroll
            for (int kk = 0; kk < 4; ++kk)
                ldsm4(qf[kk], Qs + (warp * 16 + (lane & 15)) * 72 +
                              kk * 16 + ((lane >> 4) << 3));
        }

        char* base = smc + 18432 + cur * 27648;
        const __half* Ks = (const __half*)base;
        const __nv_bfloat16* Vh_ = (const __nv_bfloat16*)(base + 9216);
        const __nv_bfloat16* Vl_ = (const __nv_bfloat16*)(base + 18432);
        const int n0 = it * 64;

        // S = Q K^T (fp16 single plane, log2 domain)
        float sc[8][4];
        #pragma unroll
        for (int j = 0; j < 8; ++j)
            #pragma unroll
            for (int q = 0; q < 4; ++q) sc[j][q] = 0.f;

        #pragma unroll
        for (int kk = 0; kk < 4; ++kk) {
            #pragma unroll
            for (int p = 0; p < 4; ++p) {
                const int krow = p * 16 + (lane & 7) + ((lane >> 4) << 3);
                const int kcol = kk * 16 + (((lane >> 3) & 1) << 3);
                unsigned kb[4];
                ldsm4(kb, Ks + krow * 72 + kcol);
                #pragma unroll
                for (int jj = 0; jj < 2; ++jj)
                    mma_f16(sc[2 * p + jj], qf[kk], kb[2 * jj], kb[2 * jj + 1]);
            }
        }

        // causal mask
        const int r0 = m0 + warp * 16 + g, r1 = r0 + 8;
        if (n0 + 63 > m0) {
            #pragma unroll
            for (int j = 0; j < 8; ++j) {
                int cb = n0 + j * 8 + 2 * tg;
                if (cb > r0) sc[j][0] = -1e30f;
                if (cb + 1 > r0) sc[j][1] = -1e30f;
                if (cb > r1) sc[j][2] = -1e30f;
                if (cb + 1 > r1) sc[j][3] = -1e30f;
            }
        }

        // online softmax, base-2
        #pragma unroll
        for (int r = 0; r < 2; ++r) {
            float mx = -1e30f;
            #pragma unroll
            for (int j = 0; j < 8; ++j)
                mx = fmaxf(mx, fmaxf(sc[j][2 * r], sc[j][2 * r + 1]));
            mx = fmaxf(mx, __shfl_xor_sync(0xffffffffu, mx, 1));
            mx = fmaxf(mx, __shfl_xor_sync(0xffffffffu, mx, 2));
            float mnew = fmaxf(mrow[r], mx);
            float alpha = exp2p(mrow[r] - mnew);
            mrow[r] = mnew;
            float rsum = 0.f;
            #pragma unroll
            for (int j = 0; j < 8; ++j) {
                float p0 = exp2p(sc[j][2 * r] - mnew);
                float p1 = exp2p(sc[j][2 * r + 1] - mnew);
                sc[j][2 * r] = p0; sc[j][2 * r + 1] = p1;
                rsum += p0 + p1;
            }
            rsum += __shfl_xor_sync(0xffffffffu, rsum, 1);
            rsum += __shfl_xor_sync(0xffffffffu, rsum, 2);
            lrow[r] = lrow[r] * alpha + rsum;
            #pragma unroll
            for (int j = 0; j < 8; ++j) {
                o[j][2 * r] *= alpha;
                o[j][2 * r + 1] *= alpha;
            }
        }

        // O += P V (P split bf16 hi/lo, V bf16 hi/lo: 3-term)
        #pragma unroll
        for (int s = 0; s < 4; ++s) {
            unsigned pah[4], pal[4];
            split_pk(sc[2 * s][0], sc[2 * s][1], pah[0], pal[0]);
            split_pk(sc[2 * s][2], sc[2 * s][3], pah[1], pal[1]);
            split_pk(sc[2 * s + 1][0], sc[2 * s + 1][1], pah[2], pal[2]);
            split_pk(sc[2 * s + 1][2], sc[2 * s + 1][3], pah[3], pal[3]);
            #pragma unroll
            for (int p = 0; p < 4; ++p) {
                const int vrow = s * 16 + (lane & 15);
                const int vcol = p * 16 + ((lane >> 4) << 3);
                unsigned vbh[4], vbl[4];
                ldsm4t(vbh, Vh_ + vrow * 72 + vcol);
                ldsm4t(vbl, Vl_ + vrow * 72 + vcol);
                #pragma unroll
                for (int jj = 0; jj < 2; ++jj) {
                    float* c = o[2 * p + jj];
                    mma_bf16(c, pah, vbh[2 * jj], vbh[2 * jj + 1]);
                    mma_bf16(c, pah, vbl[2 * jj], vbl[2 * jj + 1]);
                    mma_bf16(c, pal, vbh[2 * jj], vbh[2 * jj + 1]);
                }
            }
        }

        if (it + 2 < nt) {
            load_kv(it + 2, ldb);
            cp_commit();
        }
        cur = (cur == 2) ? 0 : cur + 1;
        ldb = (ldb == 2) ? 0 : ldb + 1;
    }

    // epilogue: normalize, write ctx hi/lo
    const float inv0 = 1.f / lrow[0], inv1 = 1.f / lrow[1];
    const int t0 = m0 + warp * 16 + g, t1 = t0 + 8;
    #pragma unroll
    for (int j = 0; j < 8; ++j) {
        int col = h * DD + j * 8 + 2 * tg;
        unsigned hh, ll;
        split_pk(o[j][0] * inv0, o[j][1] * inv0, hh, ll);
        *(unsigned*)(ch + (bt0 + t0) * CC + col) = hh;
        *(unsigned*)(cl + (bt0 + t0) * CC + col) = ll;
        split_pk(o[j][2] * inv1, o[j][3] * inv1, hh, ll);
        *(unsigned*)(ch + (bt0 + t1) * CC + col) = hh;
        *(unsigned*)(cl + (bt0 + t1) * CC + col) = ll;
    }
}

// ----------------------------------------------------------------------------
extern "C" void kernel_launch(void* const* d_in, const int* in_sizes, int n_in,
                              void* d_out, int out_size)
{
    const float* x     = (const float*)d_in[0];
    const float* w_qkv = (const float*)d_in[1];
    const float* w_out = (const float*)d_in[2];
    const float* b_out = (const float*)d_in[3];
    float* out = (float*)d_out;

    __nv_bfloat16 *xh, *xl, *wqh, *wql, *woh, *wol, *vh, *vl, *ctxh, *ctxl;
    __half* qk16;
    cudaGetSymbolAddress((void**)&xh, g_xh);
    cudaGetSymbolAddress((void**)&xl, g_xl);
    cudaGetSymbolAddress((void**)&wqh, g_wqh);
    cudaGetSymbolAddress((void**)&wql, g_wql);
    cudaGetSymbolAddress((void**)&woh, g_woh);
    cudaGetSymbolAddress((void**)&wol, g_wol);
    cudaGetSymbolAddress((void**)&qk16, g_qk16);
    cudaGetSymbolAddress((void**)&vh, g_vh);
    cudaGetSymbolAddress((void**)&vl, g_vl);
    cudaGetSymbolAddress((void**)&ctxh, g_ctxh);
    cudaGetSymbolAddress((void**)&ctxl, g_ctxl);

    static bool attr_set = false;
    if (!attr_set) {
        cudaFuncSetAttribute(gemm_sp<true, false>,
                             cudaFuncAttributeMaxDynamicSharedMemorySize, GEMM_SMEM);
        cudaFuncSetAttribute(gemm_sp<false, true>,
                             cudaFuncAttributeMaxDynamicSharedMemorySize, GEMM_SMEM);
        cudaFuncSetAttribute(attn_tc,
                             cudaFuncAttributeMaxDynamicSharedMemorySize, ATTN_SMEM);
        attr_set = true;
    }

    const int M = BB * TT;
    const float QSCALE = 0.125f * 1.44269504f;  // D^-0.5 * log2(e)

    // 0) split inputs into bf16 hi/lo planes
    {
        int n2;
        n2 = M * CC / 2;
        split_kernel<<<(n2 + 255) / 256, 256>>>((const float2*)x, (unsigned*)xh, (unsigned*)xl, n2);
        n2 = CC * 3 * CC / 2;
        split_kernel<<<(n2 + 255) / 256, 256>>>((const float2*)w_qkv, (unsigned*)wqh, (unsigned*)wql, n2);
        n2 = CC * CC / 2;
        split_kernel<<<(n2 + 255) / 256, 256>>>((const float2*)w_out, (unsigned*)woh, (unsigned*)wol, n2);
    }

    // 1) qkv = x @ w_qkv -> q,k fp16 (q in log2 domain), v bf16 hi/lo
    gemm_sp<true, false><<<dim3(3 * CC / 128, M / 128), 256, GEMM_SMEM>>>(
        xh, xl, wqh, wql, nullptr, qk16, vh, vl, nullptr, M, 3 * CC, CC, QSCALE, CC);

    // 2) causal flash attention (fp16 S, bf16x3 PV) -> ctx hi/lo
    attn_tc<<<dim3(TT / 128, BB * HH), 256, ATTN_SMEM>>>(qk16, vh, vl, ctxh, ctxl);

    // 3) out = ctx @ w_out + b_out
    gemm_sp<false, true><<<dim3(CC / 128, M / 128), 256, GEMM_SMEM>>>(
        ctxh, ctxl, woh, wol, out, nullptr, nullptr, nullptr, b_out, M, CC, CC, 1.f, 0);
}

// round 7
// speedup vs baseline: 5.7919x; 1.6484x over previous
#include <cuda_runtime.h>
#include <cuda_bf16.h>
#include <cuda_fp16.h>
#include <math.h>

#define BB 4
#define TT 2048
#define CC 1024
#define HH 16
#define DD 64
// M = BB*TT = 8192

// ---------------- scratch (device globals; no allocations) ------------------
__device__ __half        g_x16[(size_t)BB * TT * CC];       // x fp16
__device__ __half        g_w16[(size_t)CC * 3 * CC];        // w_qkv fp16
__device__ __nv_bfloat16 g_woh[(size_t)CC * CC];            // w_out bf16 hi
__device__ __nv_bfloat16 g_wol[(size_t)CC * CC];            // w_out bf16 lo
__device__ __half        g_qkv16[(size_t)BB * TT * 3 * CC]; // q(scaled)|k|v fp16
__device__ __nv_bfloat16 g_ctxh[(size_t)BB * TT * CC];
__device__ __nv_bfloat16 g_ctxl[(size_t)BB * TT * CC];

// ---------------- helpers ----------------------------------------------------
__device__ __forceinline__ unsigned pk2(float lo, float hi) {
    unsigned r;
    asm("cvt.rn.bf16x2.f32 %0, %1, %2;" : "=r"(r) : "f"(hi), "f"(lo));
    return r;
}
__device__ __forceinline__ unsigned pkh2(float lo, float hi) {
    unsigned r;
    asm("cvt.rn.f16x2.f32 %0, %1, %2;" : "=r"(r) : "f"(hi), "f"(lo));
    return r;
}
__device__ __forceinline__ void split_pk(float x0, float x1, unsigned& h, unsigned& l) {
    h = pk2(x0, x1);
    float h0 = __int_as_float(h << 16);
    float h1 = __int_as_float(h & 0xFFFF0000u);
    l = pk2(x0 - h0, x1 - h1);
}
__device__ __forceinline__ void mma_bf16(float* c, const unsigned* a,
                                         unsigned b0, unsigned b1) {
    asm volatile(
        "mma.sync.aligned.m16n8k16.row.col.f32.bf16.bf16.f32 "
        "{%0,%1,%2,%3}, {%4,%5,%6,%7}, {%8,%9}, {%0,%1,%2,%3};"
        : "+f"(c[0]), "+f"(c[1]), "+f"(c[2]), "+f"(c[3])
        : "r"(a[0]), "r"(a[1]), "r"(a[2]), "r"(a[3]), "r"(b0), "r"(b1));
}
__device__ __forceinline__ void mma_f16(float* c, const unsigned* a,
                                        unsigned b0, unsigned b1) {
    asm volatile(
        "mma.sync.aligned.m16n8k16.row.col.f32.f16.f16.f32 "
        "{%0,%1,%2,%3}, {%4,%5,%6,%7}, {%8,%9}, {%0,%1,%2,%3};"
        : "+f"(c[0]), "+f"(c[1]), "+f"(c[2]), "+f"(c[3])
        : "r"(a[0]), "r"(a[1]), "r"(a[2]), "r"(a[3]), "r"(b0), "r"(b1));
}
__device__ __forceinline__ void ldsm4(unsigned* r, const void* p) {
    unsigned a = (unsigned)__cvta_generic_to_shared(p);
    asm volatile("ldmatrix.sync.aligned.m8n8.x4.shared.b16 {%0,%1,%2,%3}, [%4];"
                 : "=r"(r[0]), "=r"(r[1]), "=r"(r[2]), "=r"(r[3]) : "r"(a));
}
__device__ __forceinline__ void ldsm4t(unsigned* r, const void* p) {
    unsigned a = (unsigned)__cvta_generic_to_shared(p);
    asm volatile("ldmatrix.sync.aligned.m8n8.x4.trans.shared.b16 {%0,%1,%2,%3}, [%4];"
                 : "=r"(r[0]), "=r"(r[1]), "=r"(r[2]), "=r"(r[3]) : "r"(a));
}
__device__ __forceinline__ void cp16(const void* sdst, const void* gsrc) {
    unsigned d = (unsigned)__cvta_generic_to_shared(sdst);
    asm volatile("cp.async.ca.shared.global [%0], [%1], 16;" :: "r"(d), "l"(gsrc));
}
__device__ __forceinline__ void cp_commit() { asm volatile("cp.async.commit_group;"); }

// exp2 via magic-round + poly (FMA pipe only, no MUFU)
__device__ __forceinline__ float exp2p(float p) {
    p = fmaxf(p, -120.f);
    float t = p + 12582912.f;
    int ii = __float_as_int(t) - 0x4B400000;
    float f = p - (t - 12582912.f);
    float r = 1.5403530e-4f;
    r = fmaf(r, f, 1.3333558e-3f);
    r = fmaf(r, f, 9.6181291e-3f);
    r = fmaf(r, f, 5.5504109e-2f);
    r = fmaf(r, f, 2.4022651e-1f);
    r = fmaf(r, f, 6.9314718e-1f);
    r = fmaf(r, f, 1.0f);
    return r * __int_as_float((ii + 127) << 23);
}

// ---------------- convert kernels ---------------------------------------------
__global__ void conv16_kernel(const float2* __restrict__ src,
                              __half2* __restrict__ dst, int n2)
{
    int i = blockIdx.x * blockDim.x + threadIdx.x;
    if (i < n2) {
        float2 v = src[i];
        dst[i] = __floats2half2_rn(v.x, v.y);
    }
}
__global__ void split_kernel(const float2* __restrict__ src,
                             unsigned* __restrict__ hi, unsigned* __restrict__ lo, int n2)
{
    int i = blockIdx.x * blockDim.x + threadIdx.x;
    if (i < n2) {
        float2 v = src[i];
        unsigned h, l;
        split_pk(v.x, v.y, h, l);
        hi[i] = h; lo[i] = l;
    }
}

// ---------------- fp16 single-plane GEMM (QKV) ----------------------------------
// qkv[M,3C] = x[M,C] @ w[C,3C], fp16 in, fp32 accum, fp16 out (q cols scaled).
// BM=BN=128, BK=32, 256 thr, 3-stage cp.async pipeline.
#define GEMM16_SMEM 56832
__global__ __launch_bounds__(256, 2)
void gemm_f16(const __half* __restrict__ A, const __half* __restrict__ B,
              __half* __restrict__ C, int M, int N, int K,
              float qscale, int qcols)
{
    extern __shared__ __half smh[];
    const int tid = threadIdx.x, warp = tid >> 5, lane = tid & 31;
    const int wm = warp & 3, wn = warp >> 2;
    const int bm = blockIdx.y * 128, bn = blockIdx.x * 128;

    auto As = [&](int buf) { return smh + buf * 9472; };
    auto Bs = [&](int buf) { return smh + buf * 9472 + 5120; };

    float acc[2][8][4];
    #pragma unroll
    for (int i = 0; i < 2; ++i)
        #pragma unroll
        for (int j = 0; j < 8; ++j)
            #pragma unroll
            for (int q = 0; q < 4; ++q) acc[i][j][q] = 0.f;

    auto loadbuf = [&](int buf, int k0) {
        #pragma unroll
        for (int c = 0; c < 2; ++c) {
            int id = tid + c * 256;                 // 0..511
            int row = id >> 2, col8 = (id & 3) << 3;
            cp16(As(buf) + row * 40 + col8, A + (size_t)(bm + row) * K + k0 + col8);
        }
        #pragma unroll
        for (int c = 0; c < 2; ++c) {
            int id = tid + c * 256;
            int row = id >> 4, col8 = (id & 15) << 3;
            cp16(Bs(buf) + row * 136 + col8, B + (size_t)(k0 + row) * N + bn + col8);
        }
    };

    const int iters = K >> 5;
    loadbuf(0, 0);  cp_commit();
    loadbuf(1, 32); cp_commit();

    int cur = 0, ldb = 2;
    for (int it = 0; it < iters; ++it) {
        if (it + 1 < iters) asm volatile("cp.async.wait_group 1;" ::: "memory");
        else                asm volatile("cp.async.wait_group 0;" ::: "memory");
        __syncthreads();

        #pragma unroll
        for (int kk = 0; kk < 2; ++kk) {
            unsigned af[2][4];
            #pragma unroll
            for (int i = 0; i < 2; ++i)
                ldsm4(af[i], As(cur) +
                      (wm * 32 + i * 16 + (lane & 15)) * 40 + kk * 16 + ((lane >> 4) << 3));
            #pragma unroll
            for (int p = 0; p < 4; ++p) {
                unsigned bf_[4];
                ldsm4t(bf_, Bs(cur) +
                       (kk * 16 + (lane & 15)) * 136 + wn * 64 + p * 16 + ((lane >> 4) << 3));
                #pragma unroll
                for (int i = 0; i < 2; ++i)
                    #pragma unroll
                    for (int jj = 0; jj < 2; ++jj)
                        mma_f16(acc[i][2 * p + jj], af[i], bf_[2 * jj], bf_[2 * jj + 1]);
            }
        }

        if (it + 2 < iters) {
            loadbuf(ldb, (it + 2) << 5);
            cp_commit();
        }
        cur = (cur == 2) ? 0 : cur + 1;
        ldb = (ldb == 2) ? 0 : ldb + 1;
    }

    // epilogue: fp16 out, scale q columns
    const int g = lane >> 2, tg = lane & 3;
    #pragma unroll
    for (int i = 0; i < 2; ++i) {
        int row0 = bm + wm * 32 + i * 16 + g;
        #pragma unroll
        for (int j = 0; j < 8; ++j) {
            int col = bn + wn * 64 + j * 8 + 2 * tg;
            float fac = (col < qcols) ? qscale : 1.f;
            *(__half2*)(C + (size_t)row0 * N + col) =
                __floats2half2_rn(acc[i][j][0] * fac, acc[i][j][1] * fac);
            *(__half2*)(C + (size_t)(row0 + 8) * N + col) =
                __floats2half2_rn(acc[i][j][2] * fac, acc[i][j][3] * fac);
        }
    }
}

// ---------------- bf16x3 GEMM (out projection) ----------------------------------
// out[M,N] = ctx[M,K](hi/lo) @ w[K,N](hi/lo) + bias, fp32 out.
#define GEMM_SMEM 113664
__global__ __launch_bounds__(256, 2)
void gemm_sp(const __nv_bfloat16* __restrict__ Ah, const __nv_bfloat16* __restrict__ Al,
             const __nv_bfloat16* __restrict__ Bh, const __nv_bfloat16* __restrict__ Bl,
             float* __restrict__ Cf, const float* __restrict__ bias,
             int M, int N, int K)
{
    extern __shared__ __nv_bfloat16 sm[];
    const int tid = threadIdx.x, warp = tid >> 5, lane = tid & 31;
    const int wm = warp & 3, wn = warp >> 2;
    const int bm = blockIdx.y * 128, bn = blockIdx.x * 128;

    auto As = [&](int buf, int t) { return sm + buf * 18944 + t * 5120; };
    auto Bs = [&](int buf, int t) { return sm + buf * 18944 + 10240 + t * 4352; };

    float acc[2][8][4];
    #pragma unroll
    for (int i = 0; i < 2; ++i)
        #pragma unroll
        for (int j = 0; j < 8; ++j)
            #pragma unroll
            for (int q = 0; q < 4; ++q) acc[i][j][q] = 0.f;

    auto loadbuf = [&](int buf, int k0) {
        #pragma unroll
        for (int t = 0; t < 2; ++t) {
            const __nv_bfloat16* Ag = t ? Al : Ah;
            #pragma unroll
            for (int c = 0; c < 2; ++c) {
                int id = tid + c * 256;
                int row = id >> 2, col8 = (id & 3) << 3;
                cp16(As(buf, t) + row * 40 + col8,
                     Ag + (size_t)(bm + row) * K + k0 + col8);
            }
            const __nv_bfloat16* Bg = t ? Bl : Bh;
            #pragma unroll
            for (int c = 0; c < 2; ++c) {
                int id = tid + c * 256;
                int row = id >> 4, col8 = (id & 15) << 3;
                cp16(Bs(buf, t) + row * 136 + col8,
                     Bg + (size_t)(k0 + row) * N + bn + col8);
            }
        }
    };

    const int iters = K >> 5;
    loadbuf(0, 0);  cp_commit();
    loadbuf(1, 32); cp_commit();

    int cur = 0, ldb = 2;
    for (int it = 0; it < iters; ++it) {
        if (it + 1 < iters) asm volatile("cp.async.wait_group 1;" ::: "memory");
        else                asm volatile("cp.async.wait_group 0;" ::: "memory");
        __syncthreads();

        #pragma unroll
        for (int kk = 0; kk < 2; ++kk) {
            unsigned af[2][2][4];
            #pragma unroll
            for (int i = 0; i < 2; ++i)
                #pragma unroll
                for (int t = 0; t < 2; ++t)
                    ldsm4(af[i][t], As(cur, t) +
                          (wm * 32 + i * 16 + (lane & 15)) * 40 + kk * 16 + ((lane >> 4) << 3));
            #pragma unroll
            for (int p = 0; p < 4; ++p) {
                unsigned bh_[4], bl_[4];
                ldsm4t(bh_, Bs(cur, 0) +
                       (kk * 16 + (lane & 15)) * 136 + wn * 64 + p * 16 + ((lane >> 4) << 3));
                ldsm4t(bl_, Bs(cur, 1) +
                       (kk * 16 + (lane & 15)) * 136 + wn * 64 + p * 16 + ((lane >> 4) << 3));
                #pragma unroll
                for (int i = 0; i < 2; ++i)
                    #pragma unroll
                    for (int jj = 0; jj < 2; ++jj) {
                        float* c = acc[i][2 * p + jj];
                        mma_bf16(c, af[i][0], bh_[2 * jj], bh_[2 * jj + 1]);
                        mma_bf16(c, af[i][0], bl_[2 * jj], bl_[2 * jj + 1]);
                        mma_bf16(c, af[i][1], bh_[2 * jj], bh_[2 * jj + 1]);
                    }
            }
        }

        if (it + 2 < iters) {
            loadbuf(ldb, (it + 2) << 5);
            cp_commit();
        }
        cur = (cur == 2) ? 0 : cur + 1;
        ldb = (ldb == 2) ? 0 : ldb + 1;
    }

    const int g = lane >> 2, tg = lane & 3;
    #pragma unroll
    for (int i = 0; i < 2; ++i) {
        int row0 = bm + wm * 32 + i * 16 + g;
        #pragma unroll
        for (int j = 0; j < 8; ++j) {
            int col = bn + wn * 64 + j * 8 + 2 * tg;
            float b0 = bias[col], b1 = bias[col + 1];
            float2 w0 = make_float2(acc[i][j][0] + b0, acc[i][j][1] + b1);
            float2 w1 = make_float2(acc[i][j][2] + b0, acc[i][j][3] + b1);
            *(float2*)&Cf[(size_t)row0 * N + col] = w0;
            *(float2*)&Cf[(size_t)(row0 + 8) * N + col] = w1;
        }
    }
}

// ---------------- causal flash attention (fp16 S + fp16 PV) --------------------
// BM=128 (8 warps x 16 rows), BN=64. Q pre-scaled (log2 domain). 3-stage KV pipe.
#define ATTN_SMEM 73728
__global__ __launch_bounds__(256, 2)
void attn_tc(const __half* __restrict__ qkv,
             __nv_bfloat16* __restrict__ ch, __nv_bfloat16* __restrict__ cl)
{
    extern __shared__ char smc[];
    // Q fp16 128x72 @0 (18432 B). KV buf b @18432 + b*18432:
    //   K fp16 64x72 (+0, 9216 B), V fp16 64x72 (+9216)
    const int tid = threadIdx.x, warp = tid >> 5, lane = tid & 31;
    const int g = lane >> 2, tg = lane & 3;
    const int bh = blockIdx.y;
    const int b = bh / HH, h = bh % HH;
    const int m0 = blockIdx.x * 128;
    const size_t bt0 = (size_t)b * TT;
    const size_t rs = 3 * CC;
    const int colq = h * DD, colk = CC + h * DD, colv = 2 * CC + h * DD;

    __half* Qs = (__half*)smc;

    auto load_kv = [&](int it, int buf) {
        const int n0 = it * 64;
        char* base = smc + 18432 + buf * 18432;
        #pragma unroll
        for (int c = 0; c < 2; ++c) {
            int id = tid + c * 256;               // 0..511
            int row = id >> 3, col8 = (id & 7) << 3;
            cp16((__half*)base + row * 72 + col8,
                 qkv + (bt0 + n0 + row) * rs + colk + col8);
            cp16((__half*)(base + 9216) + row * 72 + col8,
                 qkv + (bt0 + n0 + row) * rs + colv + col8);
        }
    };

    // Q load, grouped with KV tile 0
    #pragma unroll
    for (int c = 0; c < 4; ++c) {
        int id = tid + c * 256;                   // 0..1023
        int row = id >> 3, col8 = (id & 7) << 3;
        cp16(Qs + row * 72 + col8, qkv + (bt0 + m0 + row) * rs + colq + col8);
    }
    const int nt = (m0 >> 6) + 2;
    load_kv(0, 0);
    cp_commit();
    if (nt > 1) { load_kv(1, 1); cp_commit(); }

    unsigned qf[4][4];
    float o[8][4];
    float mrow[2] = {-1e30f, -1e30f}, lrow[2] = {0.f, 0.f};
    #pragma unroll
    for (int j = 0; j < 8; ++j)
        #pragma unroll
        for (int q = 0; q < 4; ++q) o[j][q] = 0.f;

    int cur = 0, ldb = 2;
    for (int it = 0; it < nt; ++it) {
        if (it + 1 < nt) asm volatile("cp.async.wait_group 1;" ::: "memory");
        else             asm volatile("cp.async.wait_group 0;" ::: "memory");
        __syncthreads();

        if (it == 0) {
            #pragma unroll
            for (int kk = 0; kk < 4; ++kk)
                ldsm4(qf[kk], Qs + (warp * 16 + (lane & 15)) * 72 +
                              kk * 16 + ((lane >> 4) << 3));
        }

        char* base = smc + 18432 + cur * 18432;
        const __half* Ks = (const __half*)base;
        const __half* Vs = (const __half*)(base + 9216);
        const int n0 = it * 64;

        // S = Q K^T (fp16, log2 domain)
        float sc[8][4];
        #pragma unroll
        for (int j = 0; j < 8; ++j)
            #pragma unroll
            for (int q = 0; q < 4; ++q) sc[j][q] = 0.f;

        #pragma unroll
        for (int kk = 0; kk < 4; ++kk) {
            #pragma unroll
            for (int p = 0; p < 4; ++p) {
                const int krow = p * 16 + (lane & 7) + ((lane >> 4) << 3);
                const int kcol = kk * 16 + (((lane >> 3) & 1) << 3);
                unsigned kb[4];
                ldsm4(kb, Ks + krow * 72 + kcol);
                #pragma unroll
                for (int jj = 0; jj < 2; ++jj)
                    mma_f16(sc[2 * p + jj], qf[kk], kb[2 * jj], kb[2 * jj + 1]);
            }
        }

        // causal mask
        const int r0 = m0 + warp * 16 + g, r1 = r0 + 8;
        if (n0 + 63 > m0) {
            #pragma unroll
            for (int j = 0; j < 8; ++j) {
                int cb = n0 + j * 8 + 2 * tg;
                if (cb > r0) sc[j][0] = -1e30f;
                if (cb + 1 > r0) sc[j][1] = -1e30f;
                if (cb > r1) sc[j][2] = -1e30f;
                if (cb + 1 > r1) sc[j][3] = -1e30f;
            }
        }

        // online softmax, base-2
        #pragma unroll
        for (int r = 0; r < 2; ++r) {
            float mx = -1e30f;
            #pragma unroll
            for (int j = 0; j < 8; ++j)
                mx = fmaxf(mx, fmaxf(sc[j][2 * r], sc[j][2 * r + 1]));
            mx = fmaxf(mx, __shfl_xor_sync(0xffffffffu, mx, 1));
            mx = fmaxf(mx, __shfl_xor_sync(0xffffffffu, mx, 2));
            float mnew = fmaxf(mrow[r], mx);
            float alpha = exp2p(mrow[r] - mnew);
            mrow[r] = mnew;
            float rsum = 0.f;
            #pragma unroll
            for (int j = 0; j < 8; ++j) {
                float p0 = exp2p(sc[j][2 * r] - mnew);
                float p1 = exp2p(sc[j][2 * r + 1] - mnew);
                sc[j][2 * r] = p0; sc[j][2 * r + 1] = p1;
                rsum += p0 + p1;
            }
            rsum += __shfl_xor_sync(0xffffffffu, rsum, 1);
            rsum += __shfl_xor_sync(0xffffffffu, rsum, 2);
            lrow[r] = lrow[r] * alpha + rsum;
            #pragma unroll
            for (int j = 0; j < 8; ++j) {
                o[j][2 * r] *= alpha;
                o[j][2 * r + 1] *= alpha;
            }
        }

        // O += P V (both fp16, single MMA)
        #pragma unroll
        for (int s = 0; s < 4; ++s) {
            unsigned pa[4];
            pa[0] = pkh2(sc[2 * s][0], sc[2 * s][1]);
            pa[1] = pkh2(sc[2 * s][2], sc[2 * s][3]);
            pa[2] = pkh2(sc[2 * s + 1][0], sc[2 * s + 1][1]);
            pa[3] = pkh2(sc[2 * s + 1][2], sc[2 * s + 1][3]);
            #pragma unroll
            for (int p = 0; p < 4; ++p) {
                const int vrow = s * 16 + (lane & 15);
                const int vcol = p * 16 + ((lane >> 4) << 3);
                unsigned vb[4];
                ldsm4t(vb, Vs + vrow * 72 + vcol);
                #pragma unroll
                for (int jj = 0; jj < 2; ++jj)
                    mma_f16(o[2 * p + jj], pa, vb[2 * jj], vb[2 * jj + 1]);
            }
        }

        if (it + 2 < nt) {
            load_kv(it + 2, ldb);
            cp_commit();
        }
        cur = (cur == 2) ? 0 : cur + 1;
        ldb = (ldb == 2) ? 0 : ldb + 1;
    }

    // epilogue: normalize, write ctx hi/lo (bf16x3 precision for out-proj)
    const float inv0 = 1.f / lrow[0], inv1 = 1.f / lrow[1];
    const int t0 = m0 + warp * 16 + g, t1 = t0 + 8;
    #pragma unroll
    for (int j = 0; j < 8; ++j) {
        int col = h * DD + j * 8 + 2 * tg;
        unsigned hh, ll;
        split_pk(o[j][0] * inv0, o[j][1] * inv0, hh, ll);
        *(unsigned*)(ch + (bt0 + t0) * CC + col) = hh;
        *(unsigned*)(cl + (bt0 + t0) * CC + col) = ll;
        split_pk(o[j][2] * inv1, o[j][3] * inv1, hh, ll);
        *(unsigned*)(ch + (bt0 + t1) * CC + col) = hh;
        *(unsigned*)(cl + (bt0 + t1) * CC + col) = ll;
    }
}

// ----------------------------------------------------------------------------
extern "C" void kernel_launch(void* const* d_in, const int* in_sizes, int n_in,
                              void* d_out, int out_size)
{
    const float* x     = (const float*)d_in[0];
    const float* w_qkv = (const float*)d_in[1];
    const float* w_out = (const float*)d_in[2];
    const float* b_out = (const float*)d_in[3];
    float* out = (float*)d_out;

    __half *x16, *w16, *qkv16;
    __nv_bfloat16 *woh, *wol, *ctxh, *ctxl;
    cudaGetSymbolAddress((void**)&x16, g_x16);
    cudaGetSymbolAddress((void**)&w16, g_w16);
    cudaGetSymbolAddress((void**)&qkv16, g_qkv16);
    cudaGetSymbolAddress((void**)&woh, g_woh);
    cudaGetSymbolAddress((void**)&wol, g_wol);
    cudaGetSymbolAddress((void**)&ctxh, g_ctxh);
    cudaGetSymbolAddress((void**)&ctxl, g_ctxl);

    static bool attr_set = false;
    if (!attr_set) {
        cudaFuncSetAttribute(gemm_f16,
                             cudaFuncAttributeMaxDynamicSharedMemorySize, GEMM16_SMEM);
        cudaFuncSetAttribute(gemm_sp,
                             cudaFuncAttributeMaxDynamicSharedMemorySize, GEMM_SMEM);
        cudaFuncSetAttribute(attn_tc,
                             cudaFuncAttributeMaxDynamicSharedMemorySize, ATTN_SMEM);
        attr_set = true;
    }

    const int M = BB * TT;
    const float QSCALE = 0.125f * 1.44269504f;  // D^-0.5 * log2(e)

    // 0) convert x, w_qkv -> fp16; split w_out -> bf16 hi/lo
    {
        int n2;
        n2 = M * CC / 2;
        conv16_kernel<<<(n2 + 255) / 256, 256>>>((const float2*)x, (__half2*)x16, n2);
        n2 = CC * 3 * CC / 2;
        conv16_kernel<<<(n2 + 255) / 256, 256>>>((const float2*)w_qkv, (__half2*)w16, n2);
        n2 = CC * CC / 2;
        split_kernel<<<(n2 + 255) / 256, 256>>>((const float2*)w_out, (unsigned*)woh, (unsigned*)wol, n2);
    }

    // 1) qkv = x @ w_qkv (fp16 MMA), q columns pre-scaled into log2 domain
    gemm_f16<<<dim3(3 * CC / 128, M / 128), 256, GEMM16_SMEM>>>(
        x16, w16, qkv16, M, 3 * CC, CC, QSCALE, CC);

    // 2) causal flash attention (fp16 S + fp16 PV) -> ctx bf16 hi/lo
    attn_tc<<<dim3(TT / 128, BB * HH), 256, ATTN_SMEM>>>(qkv16, ctxh, ctxl);

    // 3) out = ctx @ w_out + b_out (bf16x3)
    gemm_sp<<<dim3(CC / 128, M / 128), 256, GEMM_SMEM>>>(
        ctxh, ctxl, woh, wol, out, b_out, M, CC, CC);
}

// round 8
// speedup vs baseline: 6.4338x; 1.1108x over previous
#include <cuda_runtime.h>
#include <cuda_bf16.h>
#include <cuda_fp16.h>
#include <math.h>

#define BB 4
#define TT 2048
#define CC 1024
#define HH 16
#define DD 64
// M = BB*TT = 8192

// ---------------- scratch (device globals; no allocations) ------------------
__device__ __half g_x16[(size_t)BB * TT * CC];        // x fp16
__device__ __half g_w16[(size_t)CC * 3 * CC];         // w_qkv fp16
__device__ __half g_woh[(size_t)CC * CC];             // w_out fp16 hi
__device__ __half g_wol[(size_t)CC * CC];             // w_out fp16 lo
__device__ __half g_qkv16[(size_t)BB * TT * 3 * CC];  // q(scaled)|k|v fp16
__device__ __half g_ctx16[(size_t)BB * TT * CC];      // ctx fp16

// ---------------- helpers ----------------------------------------------------
__device__ __forceinline__ unsigned pkh2(float lo, float hi) {
    unsigned r;
    asm("cvt.rn.f16x2.f32 %0, %1, %2;" : "=r"(r) : "f"(hi), "f"(lo));
    return r;
}
__device__ __forceinline__ void split_pk16(float x0, float x1, unsigned& h, unsigned& l) {
    h = pkh2(x0, x1);
    __half2 hh = *(__half2*)&h;
    float h0 = __low2float(hh), h1 = __high2float(hh);
    l = pkh2(x0 - h0, x1 - h1);
}
__device__ __forceinline__ void mma_f16(float* c, const unsigned* a,
                                        unsigned b0, unsigned b1) {
    asm volatile(
        "mma.sync.aligned.m16n8k16.row.col.f32.f16.f16.f32 "
        "{%0,%1,%2,%3}, {%4,%5,%6,%7}, {%8,%9}, {%0,%1,%2,%3};"
        : "+f"(c[0]), "+f"(c[1]), "+f"(c[2]), "+f"(c[3])
        : "r"(a[0]), "r"(a[1]), "r"(a[2]), "r"(a[3]), "r"(b0), "r"(b1));
}
__device__ __forceinline__ void ldsm4(unsigned* r, const void* p) {
    unsigned a = (unsigned)__cvta_generic_to_shared(p);
    asm volatile("ldmatrix.sync.aligned.m8n8.x4.shared.b16 {%0,%1,%2,%3}, [%4];"
                 : "=r"(r[0]), "=r"(r[1]), "=r"(r[2]), "=r"(r[3]) : "r"(a));
}
__device__ __forceinline__ void ldsm4t(unsigned* r, const void* p) {
    unsigned a = (unsigned)__cvta_generic_to_shared(p);
    asm volatile("ldmatrix.sync.aligned.m8n8.x4.trans.shared.b16 {%0,%1,%2,%3}, [%4];"
                 : "=r"(r[0]), "=r"(r[1]), "=r"(r[2]), "=r"(r[3]) : "r"(a));
}
__device__ __forceinline__ void cp16(const void* sdst, const void* gsrc) {
    unsigned d = (unsigned)__cvta_generic_to_shared(sdst);
    asm volatile("cp.async.ca.shared.global [%0], [%1], 16;" :: "r"(d), "l"(gsrc));
}
__device__ __forceinline__ void cp_commit() { asm volatile("cp.async.commit_group;"); }

// exp2, deg-4 Taylor + magic round (FMA pipe only; err ~4e-5, below fp16 pack)
__device__ __forceinline__ float exp2p(float p) {
    p = fmaxf(p, -120.f);
    float t = p + 12582912.f;
    int ii = __float_as_int(t) - 0x4B400000;
    float f = p - (t - 12582912.f);
    float r = 9.6181291e-3f;
    r = fmaf(r, f, 5.5504109e-2f);
    r = fmaf(r, f, 2.4022651e-1f);
    r = fmaf(r, f, 6.9314718e-1f);
    r = fmaf(r, f, 1.0f);
    return r * __int_as_float((ii + 127) << 23);
}

// ---------------- convert kernels ---------------------------------------------
__global__ void conv16_kernel(const float2* __restrict__ src,
                              __half2* __restrict__ dst, int n2)
{
    int i = blockIdx.x * blockDim.x + threadIdx.x;
    if (i < n2) {
        float2 v = src[i];
        dst[i] = __floats2half2_rn(v.x, v.y);
    }
}
__global__ void split16_kernel(const float2* __restrict__ src,
                               unsigned* __restrict__ hi, unsigned* __restrict__ lo, int n2)
{
    int i = blockIdx.x * blockDim.x + threadIdx.x;
    if (i < n2) {
        float2 v = src[i];
        unsigned h, l;
        split_pk16(v.x, v.y, h, l);
        hi[i] = h; lo[i] = l;
    }
}

// ---------------- fp16 single-plane GEMM (QKV) ----------------------------------
// qkv[M,3C] = x[M,C] @ w[C,3C], fp16 in, fp32 accum, fp16 out (q cols scaled).
#define GEMM16_SMEM 56832
__global__ __launch_bounds__(256, 2)
void gemm_f16(const __half* __restrict__ A, const __half* __restrict__ B,
              __half* __restrict__ C, int M, int N, int K,
              float qscale, int qcols)
{
    extern __shared__ __half smh[];
    const int tid = threadIdx.x, warp = tid >> 5, lane = tid & 31;
    const int wm = warp & 3, wn = warp >> 2;
    const int bm = blockIdx.y * 128, bn = blockIdx.x * 128;

    auto As = [&](int buf) { return smh + buf * 9472; };
    auto Bs = [&](int buf) { return smh + buf * 9472 + 5120; };

    float acc[2][8][4];
    #pragma unroll
    for (int i = 0; i < 2; ++i)
        #pragma unroll
        for (int j = 0; j < 8; ++j)
            #pragma unroll
            for (int q = 0; q < 4; ++q) acc[i][j][q] = 0.f;

    auto loadbuf = [&](int buf, int k0) {
        #pragma unroll
        for (int c = 0; c < 2; ++c) {
            int id = tid + c * 256;
            int row = id >> 2, col8 = (id & 3) << 3;
            cp16(As(buf) + row * 40 + col8, A + (size_t)(bm + row) * K + k0 + col8);
        }
        #pragma unroll
        for (int c = 0; c < 2; ++c) {
            int id = tid + c * 256;
            int row = id >> 4, col8 = (id & 15) << 3;
            cp16(Bs(buf) + row * 136 + col8, B + (size_t)(k0 + row) * N + bn + col8);
        }
    };

    const int iters = K >> 5;
    loadbuf(0, 0);  cp_commit();
    loadbuf(1, 32); cp_commit();

    int cur = 0, ldb = 2;
    for (int it = 0; it < iters; ++it) {
        if (it + 1 < iters) asm volatile("cp.async.wait_group 1;" ::: "memory");
        else                asm volatile("cp.async.wait_group 0;" ::: "memory");
        __syncthreads();

        #pragma unroll
        for (int kk = 0; kk < 2; ++kk) {
            unsigned af[2][4];
            #pragma unroll
            for (int i = 0; i < 2; ++i)
                ldsm4(af[i], As(cur) +
                      (wm * 32 + i * 16 + (lane & 15)) * 40 + kk * 16 + ((lane >> 4) << 3));
            #pragma unroll
            for (int p = 0; p < 4; ++p) {
                unsigned bf_[4];
                ldsm4t(bf_, Bs(cur) +
                       (kk * 16 + (lane & 15)) * 136 + wn * 64 + p * 16 + ((lane >> 4) << 3));
                #pragma unroll
                for (int i = 0; i < 2; ++i)
                    #pragma unroll
                    for (int jj = 0; jj < 2; ++jj)
                        mma_f16(acc[i][2 * p + jj], af[i], bf_[2 * jj], bf_[2 * jj + 1]);
            }
        }

        if (it + 2 < iters) {
            loadbuf(ldb, (it + 2) << 5);
            cp_commit();
        }
        cur = (cur == 2) ? 0 : cur + 1;
        ldb = (ldb == 2) ? 0 : ldb + 1;
    }

    const int g = lane >> 2, tg = lane & 3;
    #pragma unroll
    for (int i = 0; i < 2; ++i) {
        int row0 = bm + wm * 32 + i * 16 + g;
        #pragma unroll
        for (int j = 0; j < 8; ++j) {
            int col = bn + wn * 64 + j * 8 + 2 * tg;
            float fac = (col < qcols) ? qscale : 1.f;
            *(__half2*)(C + (size_t)row0 * N + col) =
                __floats2half2_rn(acc[i][j][0] * fac, acc[i][j][1] * fac);
            *(__half2*)(C + (size_t)(row0 + 8) * N + col) =
                __floats2half2_rn(acc[i][j][2] * fac, acc[i][j][3] * fac);
        }
    }
}

// ---------------- out-projection GEMM: fp16 A x fp16-split W (2 MMAs) ----------
// out[M,N] = ctx16[M,K] @ (Wh+Wl)[K,N] + bias, fp32 out.
#define GEMMPO_SMEM 83456
__global__ __launch_bounds__(256, 2)
void gemm_po(const __half* __restrict__ A,
             const __half* __restrict__ Bh, const __half* __restrict__ Bl,
             float* __restrict__ Cf, const float* __restrict__ bias,
             int M, int N, int K)
{
    extern __shared__ __half smh[];
    const int tid = threadIdx.x, warp = tid >> 5, lane = tid & 31;
    const int wm = warp & 3, wn = warp >> 2;
    const int bm = blockIdx.y * 128, bn = blockIdx.x * 128;

    // per buf: A 5120 halfs, Bh 4352, Bl 4352 -> 13824 halfs
    auto As  = [&](int buf) { return smh + buf * 13824; };
    auto BsH = [&](int buf) { return smh + buf * 13824 + 5120; };
    auto BsL = [&](int buf) { return smh + buf * 13824 + 9472; };

    float acc[2][8][4];
    #pragma unroll
    for (int i = 0; i < 2; ++i)
        #pragma unroll
        for (int j = 0; j < 8; ++j)
            #pragma unroll
            for (int q = 0; q < 4; ++q) acc[i][j][q] = 0.f;

    auto loadbuf = [&](int buf, int k0) {
        #pragma unroll
        for (int c = 0; c < 2; ++c) {
            int id = tid + c * 256;
            int row = id >> 2, col8 = (id & 3) << 3;
            cp16(As(buf) + row * 40 + col8, A + (size_t)(bm + row) * K + k0 + col8);
        }
        #pragma unroll
        for (int c = 0; c < 2; ++c) {
            int id = tid + c * 256;
            int row = id >> 4, col8 = (id & 15) << 3;
            cp16(BsH(buf) + row * 136 + col8, Bh + (size_t)(k0 + row) * N + bn + col8);
            cp16(BsL(buf) + row * 136 + col8, Bl + (size_t)(k0 + row) * N + bn + col8);
        }
    };

    const int iters = K >> 5;
    loadbuf(0, 0);  cp_commit();
    loadbuf(1, 32); cp_commit();

    int cur = 0, ldb = 2;
    for (int it = 0; it < iters; ++it) {
        if (it + 1 < iters) asm volatile("cp.async.wait_group 1;" ::: "memory");
        else                asm volatile("cp.async.wait_group 0;" ::: "memory");
        __syncthreads();

        #pragma unroll
        for (int kk = 0; kk < 2; ++kk) {
            unsigned af[2][4];
            #pragma unroll
            for (int i = 0; i < 2; ++i)
                ldsm4(af[i], As(cur) +
                      (wm * 32 + i * 16 + (lane & 15)) * 40 + kk * 16 + ((lane >> 4) << 3));
            #pragma unroll
            for (int p = 0; p < 4; ++p) {
                unsigned bh_[4], bl_[4];
                ldsm4t(bh_, BsH(cur) +
                       (kk * 16 + (lane & 15)) * 136 + wn * 64 + p * 16 + ((lane >> 4) << 3));
                ldsm4t(bl_, BsL(cur) +
                       (kk * 16 + (lane & 15)) * 136 + wn * 64 + p * 16 + ((lane >> 4) << 3));
                #pragma unroll
                for (int i = 0; i < 2; ++i)
                    #pragma unroll
                    for (int jj = 0; jj < 2; ++jj) {
                        float* c = acc[i][2 * p + jj];
                        mma_f16(c, af[i], bh_[2 * jj], bh_[2 * jj + 1]);
                        mma_f16(c, af[i], bl_[2 * jj], bl_[2 * jj + 1]);
                    }
            }
        }

        if (it + 2 < iters) {
            loadbuf(ldb, (it + 2) << 5);
            cp_commit();
        }
        cur = (cur == 2) ? 0 : cur + 1;
        ldb = (ldb == 2) ? 0 : ldb + 1;
    }

    const int g = lane >> 2, tg = lane & 3;
    #pragma unroll
    for (int i = 0; i < 2; ++i) {
        int row0 = bm + wm * 32 + i * 16 + g;
        #pragma unroll
        for (int j = 0; j < 8; ++j) {
            int col = bn + wn * 64 + j * 8 + 2 * tg;
            float b0 = bias[col], b1 = bias[col + 1];
            float2 w0 = make_float2(acc[i][j][0] + b0, acc[i][j][1] + b1);
            float2 w1 = make_float2(acc[i][j][2] + b0, acc[i][j][3] + b1);
            *(float2*)&Cf[(size_t)row0 * N + col] = w0;
            *(float2*)&Cf[(size_t)(row0 + 8) * N + col] = w1;
        }
    }
}

// ---------------- causal flash attention (fp16 S + fp16 PV) --------------------
// BM=128 (8 warps x 16 rows), BN=64, 3-stage KV pipe. Heavy blocks first.
#define ATTN_SMEM 73728
__global__ __launch_bounds__(256, 2)
void attn_tc(const __half* __restrict__ qkv, __half* __restrict__ ctx)
{
    extern __shared__ char smc[];
    const int tid = threadIdx.x, warp = tid >> 5, lane = tid & 31;
    const int g = lane >> 2, tg = lane & 3;
    const int bh = blockIdx.y;
    const int b = bh / HH, h = bh % HH;
    const int m0 = (gridDim.x - 1 - blockIdx.x) * 128;  // heavy blocks first
    const size_t bt0 = (size_t)b * TT;
    const size_t rs = 3 * CC;
    const int colq = h * DD, colk = CC + h * DD, colv = 2 * CC + h * DD;

    __half* Qs = (__half*)smc;

    auto load_kv = [&](int it, int buf) {
        const int n0 = it * 64;
        char* base = smc + 18432 + buf * 18432;
        #pragma unroll
        for (int c = 0; c < 2; ++c) {
            int id = tid + c * 256;
            int row = id >> 3, col8 = (id & 7) << 3;
            cp16((__half*)base + row * 72 + col8,
                 qkv + (bt0 + n0 + row) * rs + colk + col8);
            cp16((__half*)(base + 9216) + row * 72 + col8,
                 qkv + (bt0 + n0 + row) * rs + colv + col8);
        }
    };

    #pragma unroll
    for (int c = 0; c < 4; ++c) {
        int id = tid + c * 256;
        int row = id >> 3, col8 = (id & 7) << 3;
        cp16(Qs + row * 72 + col8, qkv + (bt0 + m0 + row) * rs + colq + col8);
    }
    const int nt = (m0 >> 6) + 2;
    load_kv(0, 0);
    cp_commit();
    if (nt > 1) { load_kv(1, 1); cp_commit(); }

    unsigned qf[4][4];
    float o[8][4];
    float mrow[2] = {-1e30f, -1e30f}, lrow[2] = {0.f, 0.f};
    #pragma unroll
    for (int j = 0; j < 8; ++j)
        #pragma unroll
        for (int q = 0; q < 4; ++q) o[j][q] = 0.f;

    int cur = 0, ldb = 2;
    for (int it = 0; it < nt; ++it) {
        if (it + 1 < nt) asm volatile("cp.async.wait_group 1;" ::: "memory");
        else             asm volatile("cp.async.wait_group 0;" ::: "memory");
        __syncthreads();

        if (it == 0) {
            #pragma unroll
            for (int kk = 0; kk < 4; ++kk)
                ldsm4(qf[kk], Qs + (warp * 16 + (lane & 15)) * 72 +
                              kk * 16 + ((lane >> 4) << 3));
        }

        char* base = smc + 18432 + cur * 18432;
        const __half* Ks = (const __half*)base;
        const __half* Vs = (const __half*)(base + 9216);
        const int n0 = it * 64;

        float sc[8][4];
        #pragma unroll
        for (int j = 0; j < 8; ++j)
            #pragma unroll
            for (int q = 0; q < 4; ++q) sc[j][q] = 0.f;

        #pragma unroll
        for (int kk = 0; kk < 4; ++kk) {
            #pragma unroll
            for (int p = 0; p < 4; ++p) {
                const int krow = p * 16 + (lane & 7) + ((lane >> 4) << 3);
                const int kcol = kk * 16 + (((lane >> 3) & 1) << 3);
                unsigned kb[4];
                ldsm4(kb, Ks + krow * 72 + kcol);
                #pragma unroll
                for (int jj = 0; jj < 2; ++jj)
                    mma_f16(sc[2 * p + jj], qf[kk], kb[2 * jj], kb[2 * jj + 1]);
            }
        }

        const int r0 = m0 + warp * 16 + g, r1 = r0 + 8;
        if (n0 + 63 > m0) {
            #pragma unroll
            for (int j = 0; j < 8; ++j) {
                int cb = n0 + j * 8 + 2 * tg;
                if (cb > r0) sc[j][0] = -1e30f;
                if (cb + 1 > r0) sc[j][1] = -1e30f;
                if (cb > r1) sc[j][2] = -1e30f;
                if (cb + 1 > r1) sc[j][3] = -1e30f;
            }
        }

        #pragma unroll
        for (int r = 0; r < 2; ++r) {
            float mx = -1e30f;
            #pragma unroll
            for (int j = 0; j < 8; ++j)
                mx = fmaxf(mx, fmaxf(sc[j][2 * r], sc[j][2 * r + 1]));
            mx = fmaxf(mx, __shfl_xor_sync(0xffffffffu, mx, 1));
            mx = fmaxf(mx, __shfl_xor_sync(0xffffffffu, mx, 2));
            float mnew = fmaxf(mrow[r], mx);
            float alpha = exp2p(mrow[r] - mnew);
            mrow[r] = mnew;
            float rsum = 0.f;
            #pragma unroll
            for (int j = 0; j < 8; ++j) {
                float p0 = exp2p(sc[j][2 * r] - mnew);
                float p1 = exp2p(sc[j][2 * r + 1] - mnew);
                sc[j][2 * r] = p0; sc[j][2 * r + 1] = p1;
                rsum += p0 + p1;
            }
            rsum += __shfl_xor_sync(0xffffffffu, rsum, 1);
            rsum += __shfl_xor_sync(0xffffffffu, rsum, 2);
            lrow[r] = lrow[r] * alpha + rsum;
            #pragma unroll
            for (int j = 0; j < 8; ++j) {
                o[j][2 * r] *= alpha;
                o[j][2 * r + 1] *= alpha;
            }
        }

        #pragma unroll
        for (int s = 0; s < 4; ++s) {
            unsigned pa[4];
            pa[0] = pkh2(sc[2 * s][0], sc[2 * s][1]);
            pa[1] = pkh2(sc[2 * s][2], sc[2 * s][3]);
            pa[2] = pkh2(sc[2 * s + 1][0], sc[2 * s + 1][1]);
            pa[3] = pkh2(sc[2 * s + 1][2], sc[2 * s + 1][3]);
            #pragma unroll
            for (int p = 0; p < 4; ++p) {
                const int vrow = s * 16 + (lane & 15);
                const int vcol = p * 16 + ((lane >> 4) << 3);
                unsigned vb[4];
                ldsm4t(vb, Vs + vrow * 72 + vcol);
                #pragma unroll
                for (int jj = 0; jj < 2; ++jj)
                    mma_f16(o[2 * p + jj], pa, vb[2 * jj], vb[2 * jj + 1]);
            }
        }

        if (it + 2 < nt) {
            load_kv(it + 2, ldb);
            cp_commit();
        }
        cur = (cur == 2) ? 0 : cur + 1;
        ldb = (ldb == 2) ? 0 : ldb + 1;
    }

    // epilogue: normalize, write ctx fp16 single plane
    const float inv0 = 1.f / lrow[0], inv1 = 1.f / lrow[1];
    const int t0 = m0 + warp * 16 + g, t1 = t0 + 8;
    #pragma unroll
    for (int j = 0; j < 8; ++j) {
        int col = h * DD + j * 8 + 2 * tg;
        *(unsigned*)(ctx + (bt0 + t0) * CC + col) = pkh2(o[j][0] * inv0, o[j][1] * inv0);
        *(unsigned*)(ctx + (bt0 + t1) * CC + col) = pkh2(o[j][2] * inv1, o[j][3] * inv1);
    }
}

// ----------------------------------------------------------------------------
extern "C" void kernel_launch(void* const* d_in, const int* in_sizes, int n_in,
                              void* d_out, int out_size)
{
    const float* x     = (const float*)d_in[0];
    const float* w_qkv = (const float*)d_in[1];
    const float* w_out = (const float*)d_in[2];
    const float* b_out = (const float*)d_in[3];
    float* out = (float*)d_out;

    __half *x16, *w16, *woh, *wol, *qkv16, *ctx16;
    cudaGetSymbolAddress((void**)&x16, g_x16);
    cudaGetSymbolAddress((void**)&w16, g_w16);
    cudaGetSymbolAddress((void**)&woh, g_woh);
    cudaGetSymbolAddress((void**)&wol, g_wol);
    cudaGetSymbolAddress((void**)&qkv16, g_qkv16);
    cudaGetSymbolAddress((void**)&ctx16, g_ctx16);

    static bool attr_set = false;
    if (!attr_set) {
        cudaFuncSetAttribute(gemm_f16,
                             cudaFuncAttributeMaxDynamicSharedMemorySize, GEMM16_SMEM);
        cudaFuncSetAttribute(gemm_po,
                             cudaFuncAttributeMaxDynamicSharedMemorySize, GEMMPO_SMEM);
        cudaFuncSetAttribute(attn_tc,
                             cudaFuncAttributeMaxDynamicSharedMemorySize, ATTN_SMEM);
        attr_set = true;
    }

    const int M = BB * TT;
    const float QSCALE = 0.125f * 1.44269504f;  // D^-0.5 * log2(e)

    // 0) convert x, w_qkv -> fp16; split w_out -> fp16 hi/lo
    {
        int n2;
        n2 = M * CC / 2;
        conv16_kernel<<<(n2 + 255) / 256, 256>>>((const float2*)x, (__half2*)x16, n2);
        n2 = CC * 3 * CC / 2;
        conv16_kernel<<<(n2 + 255) / 256, 256>>>((const float2*)w_qkv, (__half2*)w16, n2);
        n2 = CC * CC / 2;
        split16_kernel<<<(n2 + 255) / 256, 256>>>((const float2*)w_out,
                                                  (unsigned*)woh, (unsigned*)wol, n2);
    }

    // 1) qkv = x @ w_qkv (fp16 MMA), q columns pre-scaled into log2 domain
    gemm_f16<<<dim3(3 * CC / 128, M / 128), 256, GEMM16_SMEM>>>(
        x16, w16, qkv16, M, 3 * CC, CC, QSCALE, CC);

    // 2) causal flash attention (fp16 S + fp16 PV) -> ctx fp16
    attn_tc<<<dim3(TT / 128, BB * HH), 256, ATTN_SMEM>>>(qkv16, ctx16);

    // 3) out = ctx @ w_out + b_out (fp16 A x fp16-split W, 2 MMAs)
    gemm_po<<<dim3(CC / 128, M / 128), 256, GEMMPO_SMEM>>>(
        ctx16, woh, wol, out, b_out, M, CC, CC);
}